// round 1
// baseline (speedup 1.0000x reference)
#include <cuda_runtime.h>
#include <math.h>

#define BQ   8192
#define NCTX 4096
#define DDIM 2048
#define MDIM 1024
#define CDIM 64
#define KCLS 100

// Scratch (allocation-free rule: __device__ globals)
__device__ float g_k[(size_t)NCTX * MDIM];   // 16.8 MB
__device__ float g_v[(size_t)NCTX * MDIM];   // 16.8 MB
__device__ float g_q[(size_t)BQ * MDIM];     // 33.5 MB
__device__ float g_S[(size_t)BQ * NCTX];     // 134 MB (scores, then softmax in place)
__device__ float g_O[(size_t)BQ * MDIM];     // 33.5 MB

// ---------------------------------------------------------------------------
// Tiled SGEMM: C[M,N] = alpha * A[M,K] * op(B)
//   TRANSB=false: B is [K,N] row-major
//   TRANSB=true : B is [N,K] row-major (C = alpha * A * B^T)
// BM=BN=128, BK=8, 8x8 microtile, 256 threads. All dims divisible.
// ---------------------------------------------------------------------------
template<bool TRANSB>
__global__ __launch_bounds__(256, 2)
void sgemm_kernel(const float* __restrict__ A, const float* __restrict__ B,
                  float* __restrict__ C, int M, int N, int Kd, float alpha)
{
    constexpr int BM = 128, BN = 128, BK = 8, TM = 8, TN = 8;
    __shared__ float As[BK][BM];
    __shared__ float Bs[BK][BN];

    const int t  = threadIdx.x;
    const int bx = blockIdx.x, by = blockIdx.y;
    const int tx = t % (BN / TN);      // 0..15
    const int ty = t / (BN / TN);      // 0..15

    // A tile loader: each thread loads one float4 of A
    const int arow = t >> 1;           // 0..127
    const int acol = (t & 1) * 4;      // 0 or 4
    // B tile loader (NN): [BK][BN]
    const int brow = t >> 5;           // 0..7
    const int bcol = (t & 31) * 4;     // 0..124
    // B tile loader (NT): read rows of B[N,K]
    const int nrow = t >> 1;           // 0..127
    const int kcol = (t & 1) * 4;      // 0 or 4

    const float* Ap = A + (size_t)(by * BM + arow) * Kd + acol;

    float acc[TM][TN];
    #pragma unroll
    for (int i = 0; i < TM; i++)
        #pragma unroll
        for (int j = 0; j < TN; j++) acc[i][j] = 0.0f;

    for (int k0 = 0; k0 < Kd; k0 += BK) {
        // load A tile (transposed into As[k][m])
        float4 a4 = *(const float4*)(Ap + k0);
        As[acol + 0][arow] = a4.x;
        As[acol + 1][arow] = a4.y;
        As[acol + 2][arow] = a4.z;
        As[acol + 3][arow] = a4.w;

        if (!TRANSB) {
            float4 b4 = *(const float4*)(B + (size_t)(k0 + brow) * N + bx * BN + bcol);
            *(float4*)&Bs[brow][bcol] = b4;
        } else {
            float4 b4 = *(const float4*)(B + (size_t)(bx * BN + nrow) * Kd + k0 + kcol);
            Bs[kcol + 0][nrow] = b4.x;
            Bs[kcol + 1][nrow] = b4.y;
            Bs[kcol + 2][nrow] = b4.z;
            Bs[kcol + 3][nrow] = b4.w;
        }
        __syncthreads();

        #pragma unroll
        for (int k = 0; k < BK; k++) {
            float ra[TM], rb[TN];
            #pragma unroll
            for (int i = 0; i < TM; i += 4)
                *(float4*)&ra[i] = *(const float4*)&As[k][ty * TM + i];
            #pragma unroll
            for (int j = 0; j < TN; j += 4)
                *(float4*)&rb[j] = *(const float4*)&Bs[k][tx * TN + j];
            #pragma unroll
            for (int i = 0; i < TM; i++)
                #pragma unroll
                for (int j = 0; j < TN; j++)
                    acc[i][j] += ra[i] * rb[j];
        }
        __syncthreads();
    }

    #pragma unroll
    for (int i = 0; i < TM; i++) {
        float* Crow = C + (size_t)(by * BM + ty * TM + i) * N + bx * BN + tx * TN;
        #pragma unroll
        for (int j = 0; j < TN; j += 4) {
            float4 o;
            o.x = alpha * acc[i][j + 0];
            o.y = alpha * acc[i][j + 1];
            o.z = alpha * acc[i][j + 2];
            o.w = alpha * acc[i][j + 3];
            *(float4*)(Crow + j) = o;
        }
    }
}

// ---------------------------------------------------------------------------
// Row softmax over S[BQ][NCTX], in place. One block (256 threads) per row.
// ---------------------------------------------------------------------------
__global__ __launch_bounds__(256)
void softmax_kernel(float* __restrict__ S)
{
    const int row = blockIdx.x;
    const int t = threadIdx.x;
    float* Sr = S + (size_t)row * NCTX;
    __shared__ float red[256];

    float vals[NCTX / 256];
    float m = -INFINITY;
    #pragma unroll
    for (int i = 0; i < NCTX / 256; i++) {
        vals[i] = Sr[t + i * 256];
        m = fmaxf(m, vals[i]);
    }
    red[t] = m; __syncthreads();
    #pragma unroll
    for (int s = 128; s > 0; s >>= 1) {
        if (t < s) red[t] = fmaxf(red[t], red[t + s]);
        __syncthreads();
    }
    m = red[0]; __syncthreads();

    float sum = 0.0f;
    #pragma unroll
    for (int i = 0; i < NCTX / 256; i++) {
        vals[i] = __expf(vals[i] - m);
        sum += vals[i];
    }
    red[t] = sum; __syncthreads();
    #pragma unroll
    for (int s = 128; s > 0; s >>= 1) {
        if (t < s) red[t] += red[t + s];
        __syncthreads();
    }
    const float inv = 1.0f / red[0];

    #pragma unroll
    for (int i = 0; i < NCTX / 256; i++)
        Sr[t + i * 256] = vals[i] * inv;
}

// ---------------------------------------------------------------------------
// Fused epilogue: attended = 0.1*O + q ; LayerNorm ; fc_hash ; sigmoid ;
// binarize ; fc_cls. 4 rows per block (amortize W_hash L2 reads). 256 thr.
// Output layout: [code (BQ*CDIM)] [prob (BQ*CDIM)] [fc_cls (BQ*KCLS)]
// ---------------------------------------------------------------------------
#define EROWS 4
__global__ __launch_bounds__(256)
void epilogue_kernel(const float* __restrict__ O, const float* __restrict__ Q,
                     const float* __restrict__ Whash, const float* __restrict__ bhash,
                     const float* __restrict__ gamma, const float* __restrict__ beta,
                     const float* __restrict__ Wcls, const float* __restrict__ bcls,
                     float* __restrict__ out)
{
    const int b0 = blockIdx.x * EROWS;
    const int t = threadIdx.x;
    __shared__ float att[EROWS][MDIM];            // 16 KB
    __shared__ float red[256];
    __shared__ float part[4][EROWS][CDIM];        // 4 KB
    __shared__ float code_s[EROWS][CDIM];

    // --- residual + LayerNorm for 4 rows ---
    for (int r = 0; r < EROWS; r++) {
        const int b = b0 + r;
        float loc[MDIM / 256];
        float s = 0.0f;
        #pragma unroll
        for (int i = 0; i < MDIM / 256; i++) {
            const int m = t + i * 256;
            // match ref rounding: (a@v)*0.1 then + q (no fma contraction)
            loc[i] = __fadd_rn(__fmul_rn(0.1f, O[(size_t)b * MDIM + m]),
                               Q[(size_t)b * MDIM + m]);
            s += loc[i];
        }
        red[t] = s; __syncthreads();
        #pragma unroll
        for (int st = 128; st > 0; st >>= 1) {
            if (t < st) red[t] += red[t + st];
            __syncthreads();
        }
        const float mu = red[0] * (1.0f / MDIM);
        __syncthreads();

        float vs = 0.0f;
        #pragma unroll
        for (int i = 0; i < MDIM / 256; i++) {
            const float d = loc[i] - mu;
            vs += d * d;
        }
        red[t] = vs; __syncthreads();
        #pragma unroll
        for (int st = 128; st > 0; st >>= 1) {
            if (t < st) red[t] += red[t + st];
            __syncthreads();
        }
        const float var = red[0] * (1.0f / MDIM);
        const float rs = 1.0f / sqrtf(var + 1e-6f);
        __syncthreads();

        #pragma unroll
        for (int i = 0; i < MDIM / 256; i++) {
            const int m = t + i * 256;
            att[r][m] = (loc[i] - mu) * rs * gamma[m] + beta[m];
        }
    }
    __syncthreads();

    // --- fc_hash = normed @ W_hash + b_hash (split-K over 4 segments) ---
    {
        const int c = t & 63, seg = t >> 6;
        float acc[EROWS] = {0.f, 0.f, 0.f, 0.f};
        const int m0 = seg * (MDIM / 4);
        for (int m = m0; m < m0 + MDIM / 4; m++) {
            const float w = Whash[m * CDIM + c];
            #pragma unroll
            for (int r = 0; r < EROWS; r++) acc[r] += att[r][m] * w;
        }
        #pragma unroll
        for (int r = 0; r < EROWS; r++) part[seg][r][c] = acc[r];
    }
    __syncthreads();

    // --- sigmoid + binarize; write code & prob ---
    {
        const int c = t & 63, r = t >> 6;    // 256 threads = 4 rows * 64 cols
        const float fh = bhash[c] + part[0][r][c] + part[1][r][c]
                                  + part[2][r][c] + part[3][r][c];
        const float prob = 1.0f / (1.0f + expf(-fh));
        const float hard = (prob > 0.5f) ? 1.0f : 0.0f;
        code_s[r][c] = hard;
        const int b = b0 + r;
        out[(size_t)b * CDIM + c] = hard;                             // code
        out[(size_t)BQ * CDIM + (size_t)b * CDIM + c] = prob;         // prob
    }
    __syncthreads();

    // --- fc_cls = code @ W_cls + b_cls ---
    for (int idx = t; idx < EROWS * KCLS; idx += 256) {
        const int r = idx / KCLS, kk = idx % KCLS;
        float acc = bcls[kk];
        #pragma unroll
        for (int c = 0; c < CDIM; c++)
            acc += code_s[r][c] * Wcls[c * KCLS + kk];
        out[(size_t)BQ * CDIM * 2 + (size_t)(b0 + r) * KCLS + kk] = acc;
    }
}

// ---------------------------------------------------------------------------
extern "C" void kernel_launch(void* const* d_in, const int* in_sizes, int n_in,
                              void* d_out, int out_size)
{
    const float* feat   = (const float*)d_in[0];
    const float* emb    = (const float*)d_in[1];
    const float* W_k    = (const float*)d_in[2];
    const float* W_v    = (const float*)d_in[3];
    const float* W_q    = (const float*)d_in[4];
    const float* W_hash = (const float*)d_in[5];
    const float* b_hash = (const float*)d_in[6];
    const float* ln_g   = (const float*)d_in[7];
    const float* ln_b   = (const float*)d_in[8];
    const float* W_cls  = (const float*)d_in[9];
    const float* b_cls  = (const float*)d_in[10];
    float* out = (float*)d_out;

    float *pk, *pv, *pq, *pS, *pO;
    cudaGetSymbolAddress((void**)&pk, g_k);
    cudaGetSymbolAddress((void**)&pv, g_v);
    cudaGetSymbolAddress((void**)&pq, g_q);
    cudaGetSymbolAddress((void**)&pS, g_S);
    cudaGetSymbolAddress((void**)&pO, g_O);

    const float inv_sqrt_m = 0.03125f;  // 1/sqrt(1024)

    // k = emb @ W_k   [4096,1024]
    sgemm_kernel<false><<<dim3(MDIM / 128, NCTX / 128), 256>>>(emb, W_k, pk, NCTX, MDIM, DDIM, 1.0f);
    // v = emb @ W_v
    sgemm_kernel<false><<<dim3(MDIM / 128, NCTX / 128), 256>>>(emb, W_v, pv, NCTX, MDIM, DDIM, 1.0f);
    // q = feat @ W_q  [8192,1024]
    sgemm_kernel<false><<<dim3(MDIM / 128, BQ / 128), 256>>>(feat, W_q, pq, BQ, MDIM, DDIM, 1.0f);
    // S = q @ k^T / 32   [8192,4096]
    sgemm_kernel<true><<<dim3(NCTX / 128, BQ / 128), 256>>>(pq, pk, pS, BQ, NCTX, MDIM, inv_sqrt_m);
    // P = softmax(S) in place
    softmax_kernel<<<BQ, 256>>>(pS);
    // O = P @ v   [8192,1024]
    sgemm_kernel<false><<<dim3(MDIM / 128, BQ / 128), 256>>>(pS, pv, pO, BQ, MDIM, NCTX, 1.0f);
    // fused residual + LN + hash + binarize + classifier
    epilogue_kernel<<<BQ / EROWS, 256>>>(pO, pq, W_hash, b_hash, ln_g, ln_b, W_cls, b_cls, out);
}

// round 3
// speedup vs baseline: 1.9454x; 1.9454x over previous
#include <cuda_runtime.h>
#include <cuda_bf16.h>
#include <math.h>
#include <stdint.h>

#define BQ   8192
#define NCTX 4096
#define DDIM 2048
#define MDIM 1024
#define CDIM 64
#define KCLS 100

// SW128 swizzle on linear byte offset within a tile (128B lines = 2 rows of 64B)
#define SW(off) ((off) ^ (((off) >> 3) & 0x70))

__device__ __forceinline__ uint32_t smem_u32(const void* p) {
    uint32_t a;
    asm("{ .reg .u64 t; cvta.to.shared.u64 t, %1; cvt.u32.u64 %0, t; }" : "=r"(a) : "l"(p));
    return a;
}
__device__ __forceinline__ void cp_async16(uint32_t saddr, const void* gptr) {
    asm volatile("cp.async.cg.shared.global [%0], [%1], 16;" :: "r"(saddr), "l"(gptr) : "memory");
}
__device__ __forceinline__ void cp_commit() {
    asm volatile("cp.async.commit_group;" ::: "memory");
}
__device__ __forceinline__ void ldmx4(uint32_t* r, uint32_t addr) {
    asm volatile("ldmatrix.sync.aligned.m8n8.x4.shared.b16 {%0,%1,%2,%3}, [%4];"
                 : "=r"(r[0]), "=r"(r[1]), "=r"(r[2]), "=r"(r[3]) : "r"(addr));
}
__device__ __forceinline__ void mma16816(float* c, const uint32_t* a, uint32_t b0, uint32_t b1) {
    asm volatile("mma.sync.aligned.m16n8k16.row.col.f32.bf16.bf16.f32 "
                 "{%0,%1,%2,%3}, {%4,%5,%6,%7}, {%8,%9}, {%0,%1,%2,%3};"
                 : "+f"(c[0]), "+f"(c[1]), "+f"(c[2]), "+f"(c[3])
                 : "r"(a[0]), "r"(a[1]), "r"(a[2]), "r"(a[3]), "r"(b0), "r"(b1));
}

// ===========================================================================
// Device scratch
// ===========================================================================
__device__ __align__(256) __nv_bfloat16 g_emb1[(size_t)NCTX * DDIM];
__device__ __align__(256) __nv_bfloat16 g_emb2[(size_t)NCTX * DDIM];
__device__ __align__(256) __nv_bfloat16 g_wk1t[(size_t)MDIM * DDIM];
__device__ __align__(256) __nv_bfloat16 g_wk2t[(size_t)MDIM * DDIM];
__device__ __align__(256) __nv_bfloat16 g_wv1t[(size_t)MDIM * DDIM];
__device__ __align__(256) __nv_bfloat16 g_wv2t[(size_t)MDIM * DDIM];
__device__ __align__(256) float         g_k [(size_t)NCTX * MDIM];
__device__ __align__(256) float         g_v [(size_t)NCTX * MDIM];
__device__ __align__(256) float         g_q [(size_t)BQ * MDIM];
__device__ __align__(256) __nv_bfloat16 g_q1[(size_t)BQ * MDIM];
__device__ __align__(256) __nv_bfloat16 g_q2[(size_t)BQ * MDIM];
__device__ __align__(256) __nv_bfloat16 g_k1[(size_t)NCTX * MDIM];
__device__ __align__(256) __nv_bfloat16 g_k2[(size_t)NCTX * MDIM];
__device__ __align__(256) __nv_bfloat16 g_v1t[(size_t)MDIM * NCTX];
__device__ __align__(256) __nv_bfloat16 g_v2t[(size_t)MDIM * NCTX];
__device__ __align__(256) float         g_S [(size_t)BQ * NCTX];
__device__ __align__(256) __nv_bfloat16 g_P1[(size_t)BQ * NCTX];
__device__ __align__(256) __nv_bfloat16 g_P2[(size_t)BQ * NCTX];
__device__ __align__(256) float         g_O [(size_t)BQ * MDIM];

// ===========================================================================
// bf16x3 HMMA GEMM: C[M,N] = alpha * (A1+A2)[M,K] @ (B1+B2)[N,K]^T, drop A2B2.
// Tiles 128x128xBK32, 8 warps (2m x 4n), warp tile 64x32.
// 3-stage cp.async pipeline, SW128-swizzled smem, ldmatrix fragments.
// Grid: (N/128, M/128), 256 threads. Dynamic smem = 3*32KB.
// ===========================================================================
#define STG 3
#define STG_BYTES 32768   // A1 8K | A2 8K | B1 8K | B2 8K

__global__ __launch_bounds__(256, 1)
void hmma_gemm_kernel(const __nv_bfloat16* __restrict__ A1, const __nv_bfloat16* __restrict__ A2,
                      const __nv_bfloat16* __restrict__ B1, const __nv_bfloat16* __restrict__ B2,
                      float* __restrict__ C, int N, int Kd, float alpha)
{
    extern __shared__ char smem[];
    const int tid  = threadIdx.x;
    const int lane = tid & 31;
    const int wid  = tid >> 5;
    const int wm   = wid & 1;          // 0..1 (64-row slot)
    const int wn   = wid >> 1;         // 0..3 (32-col slot)
    const int bx = blockIdx.x, by = blockIdx.y;

    const uint32_t sbase = smem_u32(smem);
    const int nstages = Kd >> 5;

    // cp.async per-thread offsets: i = tid + h*256; r=i>>2 (0..127), c=i&3
    const int r0 = tid >> 2, c0 = (tid & 3);
    const uint32_t so0 = SW((uint32_t)(r0 * 64 + c0 * 16));
    const uint32_t so1 = SW((uint32_t)((r0 + 64) * 64 + c0 * 16));
    const size_t arowbase = ((size_t)by * 128 + r0) * Kd + c0 * 8;
    const size_t browbase = ((size_t)bx * 128 + r0) * Kd + c0 * 8;
    const size_t rowstep = (size_t)64 * Kd;

    // ldmatrix per-lane offsets
    const int a_r = lane & 15;              // row within 16
    const int a_h = (lane >> 4) * 16;       // k-half bytes
    const int b_r = (lane & 7) | ((lane >> 1) & 8);   // n row within 16
    const int b_h = ((lane >> 3) & 1) * 16;           // k-half bytes

    float acc[4][4][4];
    #pragma unroll
    for (int i = 0; i < 4; i++)
        #pragma unroll
        for (int j = 0; j < 4; j++)
            #pragma unroll
            for (int q = 0; q < 4; q++) acc[i][j][q] = 0.0f;

    // ---- issue one stage's cp.async ----
    auto issue = [&](int s) {
        const uint32_t sb = sbase + (uint32_t)((s % STG) * STG_BYTES);
        const size_t kb = (size_t)s * 32;
        const size_t ga0 = arowbase + kb, ga1 = ga0 + rowstep;
        const size_t gb0 = browbase + kb, gb1 = gb0 + rowstep;
        cp_async16(sb + so0,         A1 + ga0);
        cp_async16(sb + so1,         A1 + ga1);
        cp_async16(sb + 8192 + so0,  A2 + ga0);
        cp_async16(sb + 8192 + so1,  A2 + ga1);
        cp_async16(sb + 16384 + so0, B1 + gb0);
        cp_async16(sb + 16384 + so1, B1 + gb1);
        cp_async16(sb + 24576 + so0, B2 + gb0);
        cp_async16(sb + 24576 + so1, B2 + gb1);
        cp_commit();
    };

    issue(0);
    if (nstages > 1) issue(1);

    for (int s = 0; s < nstages; s++) {
        if (s + 2 < nstages) issue(s + 2);
        // wait until stage s is resident (FIFO group completion)
        const int after = nstages - 1 - s;
        if (after >= 2)      asm volatile("cp.async.wait_group 2;" ::: "memory");
        else if (after == 1) asm volatile("cp.async.wait_group 1;" ::: "memory");
        else                 asm volatile("cp.async.wait_group 0;" ::: "memory");
        __syncthreads();

        const uint32_t sb = sbase + (uint32_t)((s % STG) * STG_BYTES);
        #pragma unroll
        for (int p = 0; p < 3; p++) {
            const uint32_t aoff = (p == 2) ? 8192u : 0u;
            const uint32_t boff = (p == 1) ? 24576u : 16384u;
            #pragma unroll
            for (int kk = 0; kk < 2; kk++) {
                uint32_t a[4][4];
                #pragma unroll
                for (int tm = 0; tm < 4; tm++) {
                    const uint32_t off = SW((uint32_t)((wm * 64 + tm * 16 + a_r) * 64 + kk * 32 + a_h));
                    ldmx4(a[tm], sb + aoff + off);
                }
                uint32_t b[2][4];
                #pragma unroll
                for (int tn = 0; tn < 2; tn++) {
                    const uint32_t off = SW((uint32_t)((wn * 32 + tn * 16 + b_r) * 64 + kk * 32 + b_h));
                    ldmx4(b[tn], sb + boff + off);
                }
                #pragma unroll
                for (int tm = 0; tm < 4; tm++)
                    #pragma unroll
                    for (int tn8 = 0; tn8 < 4; tn8++)
                        mma16816(acc[tm][tn8], a[tm],
                                 b[tn8 >> 1][(tn8 & 1) * 2], b[tn8 >> 1][(tn8 & 1) * 2 + 1]);
            }
        }
        __syncthreads();
    }

    // ---- epilogue: write C ----
    const int crow0 = by * 128 + wm * 64 + (lane >> 2);
    const int ccol0 = bx * 128 + wn * 32 + (lane & 3) * 2;
    #pragma unroll
    for (int tm = 0; tm < 4; tm++) {
        #pragma unroll
        for (int tn8 = 0; tn8 < 4; tn8++) {
            const int rr = crow0 + tm * 16;
            const int cc = ccol0 + tn8 * 8;
            float2 v0, v1;
            v0.x = alpha * acc[tm][tn8][0]; v0.y = alpha * acc[tm][tn8][1];
            v1.x = alpha * acc[tm][tn8][2]; v1.y = alpha * acc[tm][tn8][3];
            *(float2*)(C + (size_t)rr * N + cc)       = v0;
            *(float2*)(C + (size_t)(rr + 8) * N + cc) = v1;
        }
    }
}

// ===========================================================================
// fp32 SGEMM (q only): C[M,N] = A[M,K] @ B[K,N]
// ===========================================================================
__global__ __launch_bounds__(256, 2)
void sgemm_kernel(const float* __restrict__ A, const float* __restrict__ B,
                  float* __restrict__ C, int M, int N, int Kd)
{
    constexpr int BM = 128, BN = 128, BK = 8, TM = 8, TN = 8;
    __shared__ float As[BK][BM];
    __shared__ float Bs[BK][BN];

    const int t  = threadIdx.x;
    const int bx = blockIdx.x, by = blockIdx.y;
    const int tx = t % (BN / TN);
    const int ty = t / (BN / TN);

    const int arow = t >> 1;
    const int acol = (t & 1) * 4;
    const int brow = t >> 5;
    const int bcol = (t & 31) * 4;

    const float* Ap = A + (size_t)(by * BM + arow) * Kd + acol;

    float acc[TM][TN];
    #pragma unroll
    for (int i = 0; i < TM; i++)
        #pragma unroll
        for (int j = 0; j < TN; j++) acc[i][j] = 0.0f;

    for (int k0 = 0; k0 < Kd; k0 += BK) {
        float4 a4 = *(const float4*)(Ap + k0);
        As[acol + 0][arow] = a4.x;
        As[acol + 1][arow] = a4.y;
        As[acol + 2][arow] = a4.z;
        As[acol + 3][arow] = a4.w;
        float4 b4 = *(const float4*)(B + (size_t)(k0 + brow) * N + bx * BN + bcol);
        *(float4*)&Bs[brow][bcol] = b4;
        __syncthreads();

        #pragma unroll
        for (int k = 0; k < BK; k++) {
            float ra[TM], rb[TN];
            #pragma unroll
            for (int i = 0; i < TM; i += 4)
                *(float4*)&ra[i] = *(const float4*)&As[k][ty * TM + i];
            #pragma unroll
            for (int j = 0; j < TN; j += 4)
                *(float4*)&rb[j] = *(const float4*)&Bs[k][tx * TN + j];
            #pragma unroll
            for (int i = 0; i < TM; i++)
                #pragma unroll
                for (int j = 0; j < TN; j++)
                    acc[i][j] += ra[i] * rb[j];
        }
        __syncthreads();
    }

    #pragma unroll
    for (int i = 0; i < TM; i++) {
        float* Crow = C + (size_t)(by * BM + ty * TM + i) * N + bx * BN + tx * TN;
        #pragma unroll
        for (int j = 0; j < TN; j += 4)
            *(float4*)(Crow + j) = make_float4(acc[i][j], acc[i][j+1], acc[i][j+2], acc[i][j+3]);
    }
}

// ===========================================================================
// Split fp32 -> bf16 hi/lo
// ===========================================================================
__global__ void split_kernel(const float* __restrict__ x,
                             __nv_bfloat16* __restrict__ hi, __nv_bfloat16* __restrict__ lo,
                             int n)
{
    const int i = blockIdx.x * blockDim.x + threadIdx.x;
    if (i < n) {
        const float v = x[i];
        const __nv_bfloat16 h = __float2bfloat16(v);
        hi[i] = h;
        lo[i] = __float2bfloat16(v - __bfloat162float(h));
    }
}

// Split + transpose: in[rows][cols] -> hi/lo[cols][rows]
__global__ void split_transpose_kernel(const float* __restrict__ in,
                                       __nv_bfloat16* __restrict__ hi, __nv_bfloat16* __restrict__ lo,
                                       int rows, int cols)
{
    __shared__ float tile[32][33];
    const int c0 = blockIdx.x * 32, r0 = blockIdx.y * 32;
    const int tx = threadIdx.x, ty = threadIdx.y;
    #pragma unroll
    for (int j = ty; j < 32; j += 8)
        tile[j][tx] = in[(size_t)(r0 + j) * cols + c0 + tx];
    __syncthreads();
    #pragma unroll
    for (int j = ty; j < 32; j += 8) {
        const float v = tile[tx][j];
        const __nv_bfloat16 h = __float2bfloat16(v);
        const size_t o = (size_t)(c0 + j) * rows + r0 + tx;
        hi[o] = h;
        lo[o] = __float2bfloat16(v - __bfloat162float(h));
    }
}

// ===========================================================================
// Row softmax over S[BQ][NCTX] -> bf16 hi/lo split P1,P2
// ===========================================================================
__global__ __launch_bounds__(256)
void softmax_split_kernel(const float* __restrict__ S,
                          __nv_bfloat16* __restrict__ P1, __nv_bfloat16* __restrict__ P2)
{
    const int row = blockIdx.x;
    const int t = threadIdx.x;
    const float* Sr = S + (size_t)row * NCTX;
    __shared__ float red[256];

    float vals[NCTX / 256];
    float m = -INFINITY;
    #pragma unroll
    for (int i = 0; i < NCTX / 256; i++) {
        vals[i] = Sr[t + i * 256];
        m = fmaxf(m, vals[i]);
    }
    red[t] = m; __syncthreads();
    #pragma unroll
    for (int s = 128; s > 0; s >>= 1) {
        if (t < s) red[t] = fmaxf(red[t], red[t + s]);
        __syncthreads();
    }
    m = red[0]; __syncthreads();

    float sum = 0.0f;
    #pragma unroll
    for (int i = 0; i < NCTX / 256; i++) {
        vals[i] = __expf(vals[i] - m);
        sum += vals[i];
    }
    red[t] = sum; __syncthreads();
    #pragma unroll
    for (int s = 128; s > 0; s >>= 1) {
        if (t < s) red[t] += red[t + s];
        __syncthreads();
    }
    const float inv = 1.0f / red[0];

    #pragma unroll
    for (int i = 0; i < NCTX / 256; i++) {
        const float p = vals[i] * inv;
        const __nv_bfloat16 h = __float2bfloat16(p);
        const size_t o = (size_t)row * NCTX + t + i * 256;
        P1[o] = h;
        P2[o] = __float2bfloat16(p - __bfloat162float(h));
    }
}

// ===========================================================================
// Fused epilogue
// ===========================================================================
#define EROWS 4
__global__ __launch_bounds__(256)
void epilogue_kernel(const float* __restrict__ O, const float* __restrict__ Q,
                     const float* __restrict__ Whash, const float* __restrict__ bhash,
                     const float* __restrict__ gamma, const float* __restrict__ beta,
                     const float* __restrict__ Wcls, const float* __restrict__ bcls,
                     float* __restrict__ out)
{
    const int b0 = blockIdx.x * EROWS;
    const int t = threadIdx.x;
    __shared__ float att[EROWS][MDIM];
    __shared__ float red[256];
    __shared__ float part[4][EROWS][CDIM];
    __shared__ float code_s[EROWS][CDIM];

    for (int r = 0; r < EROWS; r++) {
        const int b = b0 + r;
        float loc[MDIM / 256];
        float s = 0.0f;
        #pragma unroll
        for (int i = 0; i < MDIM / 256; i++) {
            const int m = t + i * 256;
            loc[i] = __fadd_rn(__fmul_rn(0.1f, O[(size_t)b * MDIM + m]),
                               Q[(size_t)b * MDIM + m]);
            s += loc[i];
        }
        red[t] = s; __syncthreads();
        #pragma unroll
        for (int st = 128; st > 0; st >>= 1) {
            if (t < st) red[t] += red[t + st];
            __syncthreads();
        }
        const float mu = red[0] * (1.0f / MDIM);
        __syncthreads();

        float vs = 0.0f;
        #pragma unroll
        for (int i = 0; i < MDIM / 256; i++) {
            const float d = loc[i] - mu;
            vs += d * d;
        }
        red[t] = vs; __syncthreads();
        #pragma unroll
        for (int st = 128; st > 0; st >>= 1) {
            if (t < st) red[t] += red[t + st];
            __syncthreads();
        }
        const float var = red[0] * (1.0f / MDIM);
        const float rs = 1.0f / sqrtf(var + 1e-6f);
        __syncthreads();

        #pragma unroll
        for (int i = 0; i < MDIM / 256; i++) {
            const int m = t + i * 256;
            att[r][m] = (loc[i] - mu) * rs * gamma[m] + beta[m];
        }
    }
    __syncthreads();

    {
        const int c = t & 63, seg = t >> 6;
        float acc[EROWS] = {0.f, 0.f, 0.f, 0.f};
        const int m0 = seg * (MDIM / 4);
        for (int m = m0; m < m0 + MDIM / 4; m++) {
            const float w = Whash[m * CDIM + c];
            #pragma unroll
            for (int r = 0; r < EROWS; r++) acc[r] += att[r][m] * w;
        }
        #pragma unroll
        for (int r = 0; r < EROWS; r++) part[seg][r][c] = acc[r];
    }
    __syncthreads();

    {
        const int c = t & 63, r = t >> 6;
        const float fh = bhash[c] + part[0][r][c] + part[1][r][c]
                                  + part[2][r][c] + part[3][r][c];
        const float prob = 1.0f / (1.0f + expf(-fh));
        const float hard = (prob > 0.5f) ? 1.0f : 0.0f;
        code_s[r][c] = hard;
        const int b = b0 + r;
        out[(size_t)b * CDIM + c] = hard;
        out[(size_t)BQ * CDIM + (size_t)b * CDIM + c] = prob;
    }
    __syncthreads();

    for (int idx = t; idx < EROWS * KCLS; idx += 256) {
        const int r = idx / KCLS, kk = idx % KCLS;
        float acc = bcls[kk];
        #pragma unroll
        for (int c = 0; c < CDIM; c++)
            acc += code_s[r][c] * Wcls[c * KCLS + kk];
        out[(size_t)BQ * CDIM * 2 + (size_t)(b0 + r) * KCLS + kk] = acc;
    }
}

// ===========================================================================
extern "C" void kernel_launch(void* const* d_in, const int* in_sizes, int n_in,
                              void* d_out, int out_size)
{
    const float* feat   = (const float*)d_in[0];
    const float* emb    = (const float*)d_in[1];
    const float* W_k    = (const float*)d_in[2];
    const float* W_v    = (const float*)d_in[3];
    const float* W_q    = (const float*)d_in[4];
    const float* W_hash = (const float*)d_in[5];
    const float* b_hash = (const float*)d_in[6];
    const float* ln_g   = (const float*)d_in[7];
    const float* ln_b   = (const float*)d_in[8];
    const float* W_cls  = (const float*)d_in[9];
    const float* b_cls  = (const float*)d_in[10];
    float* out = (float*)d_out;

    cudaFuncSetAttribute(hmma_gemm_kernel, cudaFuncAttributeMaxDynamicSharedMemorySize,
                         STG * STG_BYTES);

    __nv_bfloat16 *pe1, *pe2, *pwk1, *pwk2, *pwv1, *pwv2, *pq1, *pq2, *pk1, *pk2, *pv1, *pv2, *pP1, *pP2;
    float *pk, *pv, *pq, *pS, *pO;
    cudaGetSymbolAddress((void**)&pe1, g_emb1);  cudaGetSymbolAddress((void**)&pe2, g_emb2);
    cudaGetSymbolAddress((void**)&pwk1, g_wk1t); cudaGetSymbolAddress((void**)&pwk2, g_wk2t);
    cudaGetSymbolAddress((void**)&pwv1, g_wv1t); cudaGetSymbolAddress((void**)&pwv2, g_wv2t);
    cudaGetSymbolAddress((void**)&pq1, g_q1);    cudaGetSymbolAddress((void**)&pq2, g_q2);
    cudaGetSymbolAddress((void**)&pk1, g_k1);    cudaGetSymbolAddress((void**)&pk2, g_k2);
    cudaGetSymbolAddress((void**)&pv1, g_v1t);   cudaGetSymbolAddress((void**)&pv2, g_v2t);
    cudaGetSymbolAddress((void**)&pP1, g_P1);    cudaGetSymbolAddress((void**)&pP2, g_P2);
    cudaGetSymbolAddress((void**)&pk, g_k);      cudaGetSymbolAddress((void**)&pv, g_v);
    cudaGetSymbolAddress((void**)&pq, g_q);      cudaGetSymbolAddress((void**)&pS, g_S);
    cudaGetSymbolAddress((void**)&pO, g_O);

    const size_t smem_sz = STG * STG_BYTES;

    // split emb; transpose-split W_k, W_v
    split_kernel<<<(NCTX * DDIM) / 256, 256>>>(emb, pe1, pe2, NCTX * DDIM);
    split_transpose_kernel<<<dim3(MDIM / 32, DDIM / 32), dim3(32, 8)>>>(W_k, pwk1, pwk2, DDIM, MDIM);
    split_transpose_kernel<<<dim3(MDIM / 32, DDIM / 32), dim3(32, 8)>>>(W_v, pwv1, pwv2, DDIM, MDIM);

    // k = emb @ W_k, v = emb @ W_v   [4096,1024], K=2048
    hmma_gemm_kernel<<<dim3(MDIM / 128, NCTX / 128), 256, smem_sz>>>(pe1, pe2, pwk1, pwk2, pk, MDIM, DDIM, 1.0f);
    hmma_gemm_kernel<<<dim3(MDIM / 128, NCTX / 128), 256, smem_sz>>>(pe1, pe2, pwv1, pwv2, pv, MDIM, DDIM, 1.0f);

    // q = feat @ W_q (fp32 — precision-critical residual path)
    sgemm_kernel<<<dim3(MDIM / 128, BQ / 128), 256>>>(feat, W_q, pq, BQ, MDIM, DDIM);

    // splits for attention GEMMs
    split_kernel<<<(BQ * MDIM) / 256, 256>>>(pq, pq1, pq2, BQ * MDIM);
    split_kernel<<<(NCTX * MDIM) / 256, 256>>>(pk, pk1, pk2, NCTX * MDIM);
    split_transpose_kernel<<<dim3(MDIM / 32, NCTX / 32), dim3(32, 8)>>>(pv, pv1, pv2, NCTX, MDIM);

    // S = q @ k^T / 32   [8192,4096], K=1024
    hmma_gemm_kernel<<<dim3(NCTX / 128, BQ / 128), 256, smem_sz>>>(pq1, pq2, pk1, pk2, pS, NCTX, MDIM, 0.03125f);

    // P = softmax(S), split to bf16
    softmax_split_kernel<<<BQ, 256>>>(pS, pP1, pP2);

    // O = P @ v   [8192,1024], K=4096
    hmma_gemm_kernel<<<dim3(MDIM / 128, BQ / 128), 256, smem_sz>>>(pP1, pP2, pv1, pv2, pO, MDIM, NCTX, 1.0f);

    // fused residual + LN + hash + binarize + classifier
    epilogue_kernel<<<BQ / EROWS, 256>>>(pO, pq, W_hash, b_hash, ln_g, ln_b, W_cls, b_cls, out);
}

// round 7
// speedup vs baseline: 2.4001x; 1.2338x over previous
#include <cuda_runtime.h>
#include <cuda_bf16.h>
#include <math.h>
#include <stdint.h>

#define BQ   8192
#define NCTX 4096
#define DDIM 2048
#define MDIM 1024
#define CDIM 64
#define KCLS 100

#define SW(off) ((off) ^ (((off) >> 3) & 0x70))

__device__ __forceinline__ uint32_t smem_u32(const void* p) {
    uint32_t a;
    asm("{ .reg .u64 t; cvta.to.shared.u64 t, %1; cvt.u32.u64 %0, t; }" : "=r"(a) : "l"(p));
    return a;
}
__device__ __forceinline__ void cp_async16(uint32_t saddr, const void* gptr) {
    asm volatile("cp.async.cg.shared.global [%0], [%1], 16;" :: "r"(saddr), "l"(gptr) : "memory");
}
__device__ __forceinline__ void cp_commit() {
    asm volatile("cp.async.commit_group;" ::: "memory");
}
__device__ __forceinline__ void ldmx4(uint32_t* r, uint32_t addr) {
    asm volatile("ldmatrix.sync.aligned.m8n8.x4.shared.b16 {%0,%1,%2,%3}, [%4];"
                 : "=r"(r[0]), "=r"(r[1]), "=r"(r[2]), "=r"(r[3]) : "r"(addr));
}
__device__ __forceinline__ void mma16816(float* c, const uint32_t* a, uint32_t b0, uint32_t b1) {
    asm volatile("mma.sync.aligned.m16n8k16.row.col.f32.bf16.bf16.f32 "
                 "{%0,%1,%2,%3}, {%4,%5,%6,%7}, {%8,%9}, {%0,%1,%2,%3};"
                 : "+f"(c[0]), "+f"(c[1]), "+f"(c[2]), "+f"(c[3])
                 : "r"(a[0]), "r"(a[1]), "r"(a[2]), "r"(a[3]), "r"(b0), "r"(b1));
}

// ===========================================================================
// Device scratch
// ===========================================================================
__device__ __align__(256) __nv_bfloat16 g_emb1[(size_t)NCTX * DDIM];
__device__ __align__(256) __nv_bfloat16 g_emb2[(size_t)NCTX * DDIM];
__device__ __align__(256) __nv_bfloat16 g_wk1t[(size_t)MDIM * DDIM];
__device__ __align__(256) __nv_bfloat16 g_wk2t[(size_t)MDIM * DDIM];
__device__ __align__(256) __nv_bfloat16 g_wv1t[(size_t)MDIM * DDIM];
__device__ __align__(256) __nv_bfloat16 g_wv2t[(size_t)MDIM * DDIM];
__device__ __align__(256) __nv_bfloat16 g_f1[(size_t)BQ * DDIM];
__device__ __align__(256) __nv_bfloat16 g_f2[(size_t)BQ * DDIM];
__device__ __align__(256) __nv_bfloat16 g_f3[(size_t)BQ * DDIM];
__device__ __align__(256) __nv_bfloat16 g_wq1t[(size_t)MDIM * DDIM];
__device__ __align__(256) __nv_bfloat16 g_wq2t[(size_t)MDIM * DDIM];
__device__ __align__(256) __nv_bfloat16 g_wq3t[(size_t)MDIM * DDIM];
__device__ __align__(256) float         g_v [(size_t)NCTX * MDIM];
__device__ __align__(256) float         g_q [(size_t)BQ * MDIM];
__device__ __align__(256) __nv_bfloat16 g_q1[(size_t)BQ * MDIM];
__device__ __align__(256) __nv_bfloat16 g_q2[(size_t)BQ * MDIM];
__device__ __align__(256) __nv_bfloat16 g_k1[(size_t)NCTX * MDIM];
__device__ __align__(256) __nv_bfloat16 g_k2[(size_t)NCTX * MDIM];
__device__ __align__(256) __nv_bfloat16 g_v1t[(size_t)MDIM * NCTX];
__device__ __align__(256) __nv_bfloat16 g_v2t[(size_t)MDIM * NCTX];
__device__ __align__(256) float         g_S [(size_t)BQ * NCTX];
__device__ __align__(256) __nv_bfloat16 g_P1[(size_t)BQ * NCTX];
__device__ __align__(256) __nv_bfloat16 g_P2[(size_t)BQ * NCTX];
__device__ __align__(256) float         g_O [(size_t)BQ * MDIM];

// ===========================================================================
// L2 HMMA GEMM: C[M,N] = alpha*(A1+A2)@(B1+B2)^T, drop A2B2.
// Block 128x256, 8 warps (2m x 4n), warp tile 64x64, BK=32, STG=3.
// smem/stage 48KB: A1@0 A2@8K B1@16K B2@32K. Grid (N/256, M/128).
// ===========================================================================
#define STG 3
#define L2_STAGE 49152

template<bool WRITE_F32, bool SPLIT>
__global__ __launch_bounds__(256)
void hmma2_kernel(const __nv_bfloat16* __restrict__ A1, const __nv_bfloat16* __restrict__ A2,
                  const __nv_bfloat16* __restrict__ B1, const __nv_bfloat16* __restrict__ B2,
                  float* __restrict__ C, __nv_bfloat16* __restrict__ Ch, __nv_bfloat16* __restrict__ Cl,
                  int N, int Kd, float alpha)
{
    extern __shared__ char smem[];
    const int tid  = threadIdx.x;
    const int lane = tid & 31;
    const int wid  = tid >> 5;
    const int wm   = wid & 1;
    const int wn   = wid >> 1;
    const int bx = blockIdx.x, by = blockIdx.y;

    const uint32_t sbase = smem_u32(smem);
    const int nstages = Kd >> 5;

    // cp.async thread constants
    const int lr = tid >> 2, lc = tid & 3;
    const uint32_t aso0 = SW((uint32_t)(lr * 64 + lc * 16));
    const uint32_t aso1 = SW((uint32_t)((lr + 64) * 64 + lc * 16));
    uint32_t bso[4];
    #pragma unroll
    for (int h = 0; h < 4; h++) bso[h] = SW((uint32_t)((lr + h * 64) * 64 + lc * 16));
    const size_t ag0 = ((size_t)by * 128 + lr) * Kd + lc * 8;
    const size_t bg0 = ((size_t)bx * 256 + lr) * Kd + lc * 8;
    const size_t rstep = (size_t)64 * Kd;

    // ldmatrix lane maps
    const int a_r = lane & 15;
    const int a_h = (lane >> 4) * 16;
    const int b_r = (lane & 7) | ((lane >> 1) & 8);
    const int b_h = ((lane >> 3) & 1) * 16;

    float acc[4][8][4];
    #pragma unroll
    for (int i = 0; i < 4; i++)
        #pragma unroll
        for (int j = 0; j < 8; j++)
            #pragma unroll
            for (int q = 0; q < 4; q++) acc[i][j][q] = 0.0f;

    auto issue = [&](int s) {
        const uint32_t sb = sbase + (uint32_t)((s % STG) * L2_STAGE);
        const size_t kb = (size_t)s * 32;
        cp_async16(sb + aso0,        A1 + ag0 + kb);
        cp_async16(sb + aso1,        A1 + ag0 + rstep + kb);
        cp_async16(sb + 8192 + aso0, A2 + ag0 + kb);
        cp_async16(sb + 8192 + aso1, A2 + ag0 + rstep + kb);
        #pragma unroll
        for (int h = 0; h < 4; h++) {
            cp_async16(sb + 16384 + bso[h], B1 + bg0 + h * rstep + kb);
            cp_async16(sb + 32768 + bso[h], B2 + bg0 + h * rstep + kb);
        }
        cp_commit();
    };

    issue(0);
    if (nstages > 1) issue(1);

    for (int s = 0; s < nstages; s++) {
        if (s + 2 < nstages) issue(s + 2);
        const int after = nstages - 1 - s;
        if (after >= 2)      asm volatile("cp.async.wait_group 2;" ::: "memory");
        else if (after == 1) asm volatile("cp.async.wait_group 1;" ::: "memory");
        else                 asm volatile("cp.async.wait_group 0;" ::: "memory");
        __syncthreads();

        const uint32_t sb = sbase + (uint32_t)((s % STG) * L2_STAGE);
        #pragma unroll
        for (int kk = 0; kk < 2; kk++) {
            uint32_t a1f[4][4], a2f[4][4], bf[4][4];
            #pragma unroll
            for (int tm = 0; tm < 4; tm++) {
                const uint32_t off = SW((uint32_t)((wm * 64 + tm * 16 + a_r) * 64 + kk * 32 + a_h));
                ldmx4(a1f[tm], sb + off);
                ldmx4(a2f[tm], sb + 8192 + off);
            }
            #pragma unroll
            for (int tn = 0; tn < 4; tn++) {
                const uint32_t off = SW((uint32_t)((wn * 64 + tn * 16 + b_r) * 64 + kk * 32 + b_h));
                ldmx4(bf[tn], sb + 16384 + off);
            }
            #pragma unroll
            for (int tm = 0; tm < 4; tm++)
                #pragma unroll
                for (int n8 = 0; n8 < 8; n8++)
                    mma16816(acc[tm][n8], a1f[tm], bf[n8 >> 1][(n8 & 1) * 2], bf[n8 >> 1][(n8 & 1) * 2 + 1]);
            #pragma unroll
            for (int tm = 0; tm < 4; tm++)
                #pragma unroll
                for (int n8 = 0; n8 < 8; n8++)
                    mma16816(acc[tm][n8], a2f[tm], bf[n8 >> 1][(n8 & 1) * 2], bf[n8 >> 1][(n8 & 1) * 2 + 1]);
            #pragma unroll
            for (int tn = 0; tn < 4; tn++) {
                const uint32_t off = SW((uint32_t)((wn * 64 + tn * 16 + b_r) * 64 + kk * 32 + b_h));
                ldmx4(bf[tn], sb + 32768 + off);
            }
            #pragma unroll
            for (int tm = 0; tm < 4; tm++)
                #pragma unroll
                for (int n8 = 0; n8 < 8; n8++)
                    mma16816(acc[tm][n8], a1f[tm], bf[n8 >> 1][(n8 & 1) * 2], bf[n8 >> 1][(n8 & 1) * 2 + 1]);
        }
        __syncthreads();
    }

    // epilogue
    const int crow0 = by * 128 + wm * 64 + (lane >> 2);
    const int ccol0 = bx * 256 + wn * 64 + (lane & 3) * 2;
    #pragma unroll
    for (int tm = 0; tm < 4; tm++) {
        #pragma unroll
        for (int n8 = 0; n8 < 8; n8++) {
            const int cc = ccol0 + n8 * 8;
            #pragma unroll
            for (int half = 0; half < 2; half++) {
                const size_t o = (size_t)(crow0 + tm * 16 + half * 8) * N + cc;
                const float v0 = alpha * acc[tm][n8][half * 2];
                const float v1 = alpha * acc[tm][n8][half * 2 + 1];
                if (WRITE_F32) *(float2*)(C + o) = make_float2(v0, v1);
                if (SPLIT) {
                    const __nv_bfloat16 h0 = __float2bfloat16(v0);
                    const __nv_bfloat16 h1 = __float2bfloat16(v1);
                    Ch[o] = h0; Ch[o + 1] = h1;
                    Cl[o]     = __float2bfloat16(v0 - __bfloat162float(h0));
                    Cl[o + 1] = __float2bfloat16(v1 - __bfloat162float(h1));
                }
            }
        }
    }
}

// ===========================================================================
// L3 HMMA GEMM (q): C = (A1+A2+A3)@(B1+B2+B3)^T, keep products up to 2^-18.
// Block 128x128, 8 warps (2m x 4n), warp tile 64x32, BK=32, STG=3.
// smem/stage 48KB: A1@0 A2@8K A3@16K B1@24K B2@32K B3@40K.
// Writes fp32 C + bf16 hi/lo split.
// ===========================================================================
#define L3_STAGE 49152

__global__ __launch_bounds__(256)
void hmma3_kernel(const __nv_bfloat16* __restrict__ A1, const __nv_bfloat16* __restrict__ A2,
                  const __nv_bfloat16* __restrict__ A3,
                  const __nv_bfloat16* __restrict__ B1, const __nv_bfloat16* __restrict__ B2,
                  const __nv_bfloat16* __restrict__ B3,
                  float* __restrict__ C, __nv_bfloat16* __restrict__ Ch, __nv_bfloat16* __restrict__ Cl,
                  int N, int Kd)
{
    extern __shared__ char smem[];
    const int tid  = threadIdx.x;
    const int lane = tid & 31;
    const int wid  = tid >> 5;
    const int wm   = wid & 1;
    const int wn   = wid >> 1;
    const int bx = blockIdx.x, by = blockIdx.y;

    const uint32_t sbase = smem_u32(smem);
    const int nstages = Kd >> 5;

    const int lr = tid >> 2, lc = tid & 3;
    const uint32_t so0 = SW((uint32_t)(lr * 64 + lc * 16));
    const uint32_t so1 = SW((uint32_t)((lr + 64) * 64 + lc * 16));
    const size_t ag0 = ((size_t)by * 128 + lr) * Kd + lc * 8;
    const size_t bg0 = ((size_t)bx * 128 + lr) * Kd + lc * 8;
    const size_t rstep = (size_t)64 * Kd;

    const int a_r = lane & 15;
    const int a_h = (lane >> 4) * 16;
    const int b_r = (lane & 7) | ((lane >> 1) & 8);
    const int b_h = ((lane >> 3) & 1) * 16;

    float acc[4][4][4];
    #pragma unroll
    for (int i = 0; i < 4; i++)
        #pragma unroll
        for (int j = 0; j < 4; j++)
            #pragma unroll
            for (int q = 0; q < 4; q++) acc[i][j][q] = 0.0f;

    auto issue = [&](int s) {
        const uint32_t sb = sbase + (uint32_t)((s % STG) * L3_STAGE);
        const size_t kb = (size_t)s * 32;
        cp_async16(sb + so0,         A1 + ag0 + kb);
        cp_async16(sb + so1,         A1 + ag0 + rstep + kb);
        cp_async16(sb + 8192 + so0,  A2 + ag0 + kb);
        cp_async16(sb + 8192 + so1,  A2 + ag0 + rstep + kb);
        cp_async16(sb + 16384 + so0, A3 + ag0 + kb);
        cp_async16(sb + 16384 + so1, A3 + ag0 + rstep + kb);
        cp_async16(sb + 24576 + so0, B1 + bg0 + kb);
        cp_async16(sb + 24576 + so1, B1 + bg0 + rstep + kb);
        cp_async16(sb + 32768 + so0, B2 + bg0 + kb);
        cp_async16(sb + 32768 + so1, B2 + bg0 + rstep + kb);
        cp_async16(sb + 40960 + so0, B3 + bg0 + kb);
        cp_async16(sb + 40960 + so1, B3 + bg0 + rstep + kb);
        cp_commit();
    };

    issue(0);
    if (nstages > 1) issue(1);

    for (int s = 0; s < nstages; s++) {
        if (s + 2 < nstages) issue(s + 2);
        const int after = nstages - 1 - s;
        if (after >= 2)      asm volatile("cp.async.wait_group 2;" ::: "memory");
        else if (after == 1) asm volatile("cp.async.wait_group 1;" ::: "memory");
        else                 asm volatile("cp.async.wait_group 0;" ::: "memory");
        __syncthreads();

        const uint32_t sb = sbase + (uint32_t)((s % STG) * L3_STAGE);
        #pragma unroll
        for (int kk = 0; kk < 2; kk++) {
            uint32_t a1f[4][4], a2f[4][4], a3f[4][4], bf[2][4];
            #pragma unroll
            for (int tm = 0; tm < 4; tm++) {
                const uint32_t off = SW((uint32_t)((wm * 64 + tm * 16 + a_r) * 64 + kk * 32 + a_h));
                ldmx4(a1f[tm], sb + off);
                ldmx4(a2f[tm], sb + 8192 + off);
                ldmx4(a3f[tm], sb + 16384 + off);
            }
            uint32_t boff[2];
            #pragma unroll
            for (int tn = 0; tn < 2; tn++)
                boff[tn] = SW((uint32_t)((wn * 32 + tn * 16 + b_r) * 64 + kk * 32 + b_h));
            // b1: a1b1, a2b1, a3b1
            #pragma unroll
            for (int tn = 0; tn < 2; tn++) ldmx4(bf[tn], sb + 24576 + boff[tn]);
            #pragma unroll
            for (int tm = 0; tm < 4; tm++)
                #pragma unroll
                for (int n8 = 0; n8 < 4; n8++) {
                    mma16816(acc[tm][n8], a1f[tm], bf[n8 >> 1][(n8 & 1) * 2], bf[n8 >> 1][(n8 & 1) * 2 + 1]);
                    mma16816(acc[tm][n8], a2f[tm], bf[n8 >> 1][(n8 & 1) * 2], bf[n8 >> 1][(n8 & 1) * 2 + 1]);
                    mma16816(acc[tm][n8], a3f[tm], bf[n8 >> 1][(n8 & 1) * 2], bf[n8 >> 1][(n8 & 1) * 2 + 1]);
                }
            // b2: a1b2, a2b2
            #pragma unroll
            for (int tn = 0; tn < 2; tn++) ldmx4(bf[tn], sb + 32768 + boff[tn]);
            #pragma unroll
            for (int tm = 0; tm < 4; tm++)
                #pragma unroll
                for (int n8 = 0; n8 < 4; n8++) {
                    mma16816(acc[tm][n8], a1f[tm], bf[n8 >> 1][(n8 & 1) * 2], bf[n8 >> 1][(n8 & 1) * 2 + 1]);
                    mma16816(acc[tm][n8], a2f[tm], bf[n8 >> 1][(n8 & 1) * 2], bf[n8 >> 1][(n8 & 1) * 2 + 1]);
                }
            // b3: a1b3
            #pragma unroll
            for (int tn = 0; tn < 2; tn++) ldmx4(bf[tn], sb + 40960 + boff[tn]);
            #pragma unroll
            for (int tm = 0; tm < 4; tm++)
                #pragma unroll
                for (int n8 = 0; n8 < 4; n8++)
                    mma16816(acc[tm][n8], a1f[tm], bf[n8 >> 1][(n8 & 1) * 2], bf[n8 >> 1][(n8 & 1) * 2 + 1]);
        }
        __syncthreads();
    }

    const int crow0 = by * 128 + wm * 64 + (lane >> 2);
    const int ccol0 = bx * 128 + wn * 32 + (lane & 3) * 2;
    #pragma unroll
    for (int tm = 0; tm < 4; tm++) {
        #pragma unroll
        for (int n8 = 0; n8 < 4; n8++) {
            const int cc = ccol0 + n8 * 8;
            #pragma unroll
            for (int half = 0; half < 2; half++) {
                const size_t o = (size_t)(crow0 + tm * 16 + half * 8) * N + cc;
                const float v0 = acc[tm][n8][half * 2];
                const float v1 = acc[tm][n8][half * 2 + 1];
                *(float2*)(C + o) = make_float2(v0, v1);
                const __nv_bfloat16 h0 = __float2bfloat16(v0);
                const __nv_bfloat16 h1 = __float2bfloat16(v1);
                Ch[o] = h0; Ch[o + 1] = h1;
                Cl[o]     = __float2bfloat16(v0 - __bfloat162float(h0));
                Cl[o + 1] = __float2bfloat16(v1 - __bfloat162float(h1));
            }
        }
    }
}

// ===========================================================================
// Split helpers
// ===========================================================================
__global__ void split_kernel(const float* __restrict__ x,
                             __nv_bfloat16* __restrict__ hi, __nv_bfloat16* __restrict__ lo, int n)
{
    const int i = blockIdx.x * blockDim.x + threadIdx.x;
    if (i < n) {
        const float v = x[i];
        const __nv_bfloat16 h = __float2bfloat16(v);
        hi[i] = h;
        lo[i] = __float2bfloat16(v - __bfloat162float(h));
    }
}

__global__ void split3_kernel(const float* __restrict__ x,
                              __nv_bfloat16* __restrict__ h1, __nv_bfloat16* __restrict__ h2,
                              __nv_bfloat16* __restrict__ h3, int n)
{
    const int i = blockIdx.x * blockDim.x + threadIdx.x;
    if (i < n) {
        const float v = x[i];
        const __nv_bfloat16 a = __float2bfloat16(v);
        const float r1 = v - __bfloat162float(a);
        const __nv_bfloat16 b = __float2bfloat16(r1);
        h1[i] = a; h2[i] = b;
        h3[i] = __float2bfloat16(r1 - __bfloat162float(b));
    }
}

__global__ void split_transpose_kernel(const float* __restrict__ in,
                                       __nv_bfloat16* __restrict__ hi, __nv_bfloat16* __restrict__ lo,
                                       int rows, int cols)
{
    __shared__ float tile[32][33];
    const int c0 = blockIdx.x * 32, r0 = blockIdx.y * 32;
    const int tx = threadIdx.x, ty = threadIdx.y;
    #pragma unroll
    for (int j = ty; j < 32; j += 8)
        tile[j][tx] = in[(size_t)(r0 + j) * cols + c0 + tx];
    __syncthreads();
    #pragma unroll
    for (int j = ty; j < 32; j += 8) {
        const float v = tile[tx][j];
        const __nv_bfloat16 h = __float2bfloat16(v);
        const size_t o = (size_t)(c0 + j) * rows + r0 + tx;
        hi[o] = h;
        lo[o] = __float2bfloat16(v - __bfloat162float(h));
    }
}

__global__ void split3_transpose_kernel(const float* __restrict__ in,
                                        __nv_bfloat16* __restrict__ h1, __nv_bfloat16* __restrict__ h2,
                                        __nv_bfloat16* __restrict__ h3, int rows, int cols)
{
    __shared__ float tile[32][33];
    const int c0 = blockIdx.x * 32, r0 = blockIdx.y * 32;
    const int tx = threadIdx.x, ty = threadIdx.y;
    #pragma unroll
    for (int j = ty; j < 32; j += 8)
        tile[j][tx] = in[(size_t)(r0 + j) * cols + c0 + tx];
    __syncthreads();
    #pragma unroll
    for (int j = ty; j < 32; j += 8) {
        const float v = tile[tx][j];
        const __nv_bfloat16 a = __float2bfloat16(v);
        const float r1 = v - __bfloat162float(a);
        const __nv_bfloat16 b = __float2bfloat16(r1);
        const size_t o = (size_t)(c0 + j) * rows + r0 + tx;
        h1[o] = a; h2[o] = b;
        h3[o] = __float2bfloat16(r1 - __bfloat162float(b));
    }
}

// ===========================================================================
// Row softmax -> bf16 hi/lo split
// ===========================================================================
__global__ __launch_bounds__(256)
void softmax_split_kernel(const float* __restrict__ S,
                          __nv_bfloat16* __restrict__ P1, __nv_bfloat16* __restrict__ P2)
{
    const int row = blockIdx.x;
    const int t = threadIdx.x;
    const float* Sr = S + (size_t)row * NCTX;
    __shared__ float red[256];

    float vals[NCTX / 256];
    float m = -INFINITY;
    #pragma unroll
    for (int i = 0; i < NCTX / 256; i++) {
        vals[i] = Sr[t + i * 256];
        m = fmaxf(m, vals[i]);
    }
    red[t] = m; __syncthreads();
    #pragma unroll
    for (int s = 128; s > 0; s >>= 1) {
        if (t < s) red[t] = fmaxf(red[t], red[t + s]);
        __syncthreads();
    }
    m = red[0]; __syncthreads();

    float sum = 0.0f;
    #pragma unroll
    for (int i = 0; i < NCTX / 256; i++) {
        vals[i] = __expf(vals[i] - m);
        sum += vals[i];
    }
    red[t] = sum; __syncthreads();
    #pragma unroll
    for (int s = 128; s > 0; s >>= 1) {
        if (t < s) red[t] += red[t + s];
        __syncthreads();
    }
    const float inv = 1.0f / red[0];

    #pragma unroll
    for (int i = 0; i < NCTX / 256; i++) {
        const float p = vals[i] * inv;
        const __nv_bfloat16 h = __float2bfloat16(p);
        const size_t o = (size_t)row * NCTX + t + i * 256;
        P1[o] = h;
        P2[o] = __float2bfloat16(p - __bfloat162float(h));
    }
}

// ===========================================================================
// Fused epilogue
// ===========================================================================
#define EROWS 4
__global__ __launch_bounds__(256)
void epilogue_kernel(const float* __restrict__ O, const float* __restrict__ Q,
                     const float* __restrict__ Whash, const float* __restrict__ bhash,
                     const float* __restrict__ gamma, const float* __restrict__ beta,
                     const float* __restrict__ Wcls, const float* __restrict__ bcls,
                     float* __restrict__ out)
{
    const int b0 = blockIdx.x * EROWS;
    const int t = threadIdx.x;
    __shared__ float att[EROWS][MDIM];
    __shared__ float red[256];
    __shared__ float part[4][EROWS][CDIM];
    __shared__ float code_s[EROWS][CDIM];

    for (int r = 0; r < EROWS; r++) {
        const int b = b0 + r;
        float loc[MDIM / 256];
        float s = 0.0f;
        #pragma unroll
        for (int i = 0; i < MDIM / 256; i++) {
            const int m = t + i * 256;
            loc[i] = __fadd_rn(__fmul_rn(0.1f, O[(size_t)b * MDIM + m]),
                               Q[(size_t)b * MDIM + m]);
            s += loc[i];
        }
        red[t] = s; __syncthreads();
        #pragma unroll
        for (int st = 128; st > 0; st >>= 1) {
            if (t < st) red[t] += red[t + st];
            __syncthreads();
        }
        const float mu = red[0] * (1.0f / MDIM);
        __syncthreads();

        float vs = 0.0f;
        #pragma unroll
        for (int i = 0; i < MDIM / 256; i++) {
            const float d = loc[i] - mu;
            vs += d * d;
        }
        red[t] = vs; __syncthreads();
        #pragma unroll
        for (int st = 128; st > 0; st >>= 1) {
            if (t < st) red[t] += red[t + st];
            __syncthreads();
        }
        const float var = red[0] * (1.0f / MDIM);
        const float rs = 1.0f / sqrtf(var + 1e-6f);
        __syncthreads();

        #pragma unroll
        for (int i = 0; i < MDIM / 256; i++) {
            const int m = t + i * 256;
            att[r][m] = (loc[i] - mu) * rs * gamma[m] + beta[m];
        }
    }
    __syncthreads();

    {
        const int c = t & 63, seg = t >> 6;
        float acc[EROWS] = {0.f, 0.f, 0.f, 0.f};
        const int m0 = seg * (MDIM / 4);
        for (int m = m0; m < m0 + MDIM / 4; m++) {
            const float w = Whash[m * CDIM + c];
            #pragma unroll
            for (int r = 0; r < EROWS; r++) acc[r] += att[r][m] * w;
        }
        #pragma unroll
        for (int r = 0; r < EROWS; r++) part[seg][r][c] = acc[r];
    }
    __syncthreads();

    {
        const int c = t & 63, r = t >> 6;
        const float fh = bhash[c] + part[0][r][c] + part[1][r][c]
                                  + part[2][r][c] + part[3][r][c];
        const float prob = 1.0f / (1.0f + expf(-fh));
        const float hard = (prob > 0.5f) ? 1.0f : 0.0f;
        code_s[r][c] = hard;
        const int b = b0 + r;
        out[(size_t)b * CDIM + c] = hard;
        out[(size_t)BQ * CDIM + (size_t)b * CDIM + c] = prob;
    }
    __syncthreads();

    for (int idx = t; idx < EROWS * KCLS; idx += 256) {
        const int r = idx / KCLS, kk = idx % KCLS;
        float acc = bcls[kk];
        #pragma unroll
        for (int c = 0; c < CDIM; c++)
            acc += code_s[r][c] * Wcls[c * KCLS + kk];
        out[(size_t)BQ * CDIM * 2 + (size_t)(b0 + r) * KCLS + kk] = acc;
    }
}

// ===========================================================================
extern "C" void kernel_launch(void* const* d_in, const int* in_sizes, int n_in,
                              void* d_out, int out_size)
{
    const float* feat   = (const float*)d_in[0];
    const float* emb    = (const float*)d_in[1];
    const float* W_k    = (const float*)d_in[2];
    const float* W_v    = (const float*)d_in[3];
    const float* W_q    = (const float*)d_in[4];
    const float* W_hash = (const float*)d_in[5];
    const float* b_hash = (const float*)d_in[6];
    const float* ln_g   = (const float*)d_in[7];
    const float* ln_b   = (const float*)d_in[8];
    const float* W_cls  = (const float*)d_in[9];
    const float* b_cls  = (const float*)d_in[10];
    float* out = (float*)d_out;

    cudaFuncSetAttribute(hmma2_kernel<true, false>, cudaFuncAttributeMaxDynamicSharedMemorySize, STG * L2_STAGE);
    cudaFuncSetAttribute(hmma2_kernel<false, true>, cudaFuncAttributeMaxDynamicSharedMemorySize, STG * L2_STAGE);
    cudaFuncSetAttribute(hmma3_kernel, cudaFuncAttributeMaxDynamicSharedMemorySize, STG * L3_STAGE);

    __nv_bfloat16 *pe1, *pe2, *pwk1, *pwk2, *pwv1, *pwv2;
    __nv_bfloat16 *pf1, *pf2, *pf3, *pwq1, *pwq2, *pwq3;
    __nv_bfloat16 *pq1, *pq2, *pk1, *pk2, *pv1, *pv2, *pP1, *pP2;
    float *pv, *pq, *pS, *pO;
    cudaGetSymbolAddress((void**)&pe1, g_emb1);  cudaGetSymbolAddress((void**)&pe2, g_emb2);
    cudaGetSymbolAddress((void**)&pwk1, g_wk1t); cudaGetSymbolAddress((void**)&pwk2, g_wk2t);
    cudaGetSymbolAddress((void**)&pwv1, g_wv1t); cudaGetSymbolAddress((void**)&pwv2, g_wv2t);
    cudaGetSymbolAddress((void**)&pf1, g_f1);    cudaGetSymbolAddress((void**)&pf2, g_f2);
    cudaGetSymbolAddress((void**)&pf3, g_f3);
    cudaGetSymbolAddress((void**)&pwq1, g_wq1t); cudaGetSymbolAddress((void**)&pwq2, g_wq2t);
    cudaGetSymbolAddress((void**)&pwq3, g_wq3t);
    cudaGetSymbolAddress((void**)&pq1, g_q1);    cudaGetSymbolAddress((void**)&pq2, g_q2);
    cudaGetSymbolAddress((void**)&pk1, g_k1);    cudaGetSymbolAddress((void**)&pk2, g_k2);
    cudaGetSymbolAddress((void**)&pv1, g_v1t);   cudaGetSymbolAddress((void**)&pv2, g_v2t);
    cudaGetSymbolAddress((void**)&pP1, g_P1);    cudaGetSymbolAddress((void**)&pP2, g_P2);
    cudaGetSymbolAddress((void**)&pv, g_v);      cudaGetSymbolAddress((void**)&pq, g_q);
    cudaGetSymbolAddress((void**)&pS, g_S);      cudaGetSymbolAddress((void**)&pO, g_O);

    const size_t smem2 = STG * L2_STAGE;
    const size_t smem3 = STG * L3_STAGE;

    // input splits
    split_kernel<<<(NCTX * DDIM) / 256, 256>>>(emb, pe1, pe2, NCTX * DDIM);
    split_transpose_kernel<<<dim3(MDIM / 32, DDIM / 32), dim3(32, 8)>>>(W_k, pwk1, pwk2, DDIM, MDIM);
    split_transpose_kernel<<<dim3(MDIM / 32, DDIM / 32), dim3(32, 8)>>>(W_v, pwv1, pwv2, DDIM, MDIM);
    split3_kernel<<<(BQ * DDIM) / 256, 256>>>(feat, pf1, pf2, pf3, BQ * DDIM);
    split3_transpose_kernel<<<dim3(MDIM / 32, DDIM / 32), dim3(32, 8)>>>(W_q, pwq1, pwq2, pwq3, DDIM, MDIM);

    // k = emb @ W_k -> bf16 split directly (no fp32)
    hmma2_kernel<false, true><<<dim3(MDIM / 256, NCTX / 128), 256, smem2>>>(
        pe1, pe2, pwk1, pwk2, nullptr, pk1, pk2, MDIM, DDIM, 1.0f);
    // v = emb @ W_v -> fp32 (transposed split next)
    hmma2_kernel<true, false><<<dim3(MDIM / 256, NCTX / 128), 256, smem2>>>(
        pe1, pe2, pwv1, pwv2, pv, nullptr, nullptr, MDIM, DDIM, 1.0f);
    // q = feat @ W_q (triple split, 6 products) -> fp32 + hi/lo split
    hmma3_kernel<<<dim3(MDIM / 128, BQ / 128), 256, smem3>>>(
        pf1, pf2, pf3, pwq1, pwq2, pwq3, pq, pq1, pq2, MDIM, DDIM);

    split_transpose_kernel<<<dim3(MDIM / 32, NCTX / 32), dim3(32, 8)>>>(pv, pv1, pv2, NCTX, MDIM);

    // S = q @ k^T / 32
    hmma2_kernel<true, false><<<dim3(NCTX / 256, BQ / 128), 256, smem2>>>(
        pq1, pq2, pk1, pk2, pS, nullptr, nullptr, NCTX, MDIM, 0.03125f);

    softmax_split_kernel<<<BQ, 256>>>(pS, pP1, pP2);

    // O = P @ v
    hmma2_kernel<true, false><<<dim3(MDIM / 256, BQ / 128), 256, smem2>>>(
        pP1, pP2, pv1, pv2, pO, nullptr, nullptr, MDIM, NCTX, 1.0f);

    epilogue_kernel<<<BQ / EROWS, 256>>>(pO, pq, W_hash, b_hash, ln_g, ln_b, W_cls, b_cls, out);
}

// round 8
// speedup vs baseline: 2.4292x; 1.0121x over previous
#include <cuda_runtime.h>
#include <cuda_bf16.h>
#include <math.h>
#include <stdint.h>

#define BQ   8192
#define NCTX 4096
#define DDIM 2048
#define MDIM 1024
#define CDIM 64
#define KCLS 100

#define SW(off) ((off) ^ (((off) >> 3) & 0x70))

__device__ __forceinline__ uint32_t smem_u32(const void* p) {
    uint32_t a;
    asm("{ .reg .u64 t; cvta.to.shared.u64 t, %1; cvt.u32.u64 %0, t; }" : "=r"(a) : "l"(p));
    return a;
}
__device__ __forceinline__ void cp_async16(uint32_t saddr, const void* gptr) {
    asm volatile("cp.async.cg.shared.global [%0], [%1], 16;" :: "r"(saddr), "l"(gptr) : "memory");
}
__device__ __forceinline__ void cp_commit() {
    asm volatile("cp.async.commit_group;" ::: "memory");
}
__device__ __forceinline__ void ldmx4(uint32_t* r, uint32_t addr) {
    asm volatile("ldmatrix.sync.aligned.m8n8.x4.shared.b16 {%0,%1,%2,%3}, [%4];"
                 : "=r"(r[0]), "=r"(r[1]), "=r"(r[2]), "=r"(r[3]) : "r"(addr));
}
__device__ __forceinline__ void mma16816(float* c, const uint32_t* a, uint32_t b0, uint32_t b1) {
    asm volatile("mma.sync.aligned.m16n8k16.row.col.f32.bf16.bf16.f32 "
                 "{%0,%1,%2,%3}, {%4,%5,%6,%7}, {%8,%9}, {%0,%1,%2,%3};"
                 : "+f"(c[0]), "+f"(c[1]), "+f"(c[2]), "+f"(c[3])
                 : "r"(a[0]), "r"(a[1]), "r"(a[2]), "r"(a[3]), "r"(b0), "r"(b1));
}
__device__ __forceinline__ uint32_t pack_bf2(__nv_bfloat16 a, __nv_bfloat16 b) {
    __nv_bfloat162 t = __halves2bfloat162(a, b);
    return *reinterpret_cast<uint32_t*>(&t);
}

// ===========================================================================
// Device scratch
// ===========================================================================
__device__ __align__(256) __nv_bfloat16 g_emb1[(size_t)NCTX * DDIM];
__device__ __align__(256) __nv_bfloat16 g_emb2[(size_t)NCTX * DDIM];
__device__ __align__(256) __nv_bfloat16 g_wk1t[(size_t)MDIM * DDIM];
__device__ __align__(256) __nv_bfloat16 g_wk2t[(size_t)MDIM * DDIM];
__device__ __align__(256) __nv_bfloat16 g_wv1t[(size_t)MDIM * DDIM];
__device__ __align__(256) __nv_bfloat16 g_wv2t[(size_t)MDIM * DDIM];
__device__ __align__(256) __nv_bfloat16 g_f1[(size_t)BQ * DDIM];
__device__ __align__(256) __nv_bfloat16 g_f2[(size_t)BQ * DDIM];
__device__ __align__(256) __nv_bfloat16 g_f3[(size_t)BQ * DDIM];
__device__ __align__(256) __nv_bfloat16 g_wq1t[(size_t)MDIM * DDIM];
__device__ __align__(256) __nv_bfloat16 g_wq2t[(size_t)MDIM * DDIM];
__device__ __align__(256) __nv_bfloat16 g_wq3t[(size_t)MDIM * DDIM];
__device__ __align__(256) float         g_v [(size_t)NCTX * MDIM];
__device__ __align__(256) float         g_q [(size_t)BQ * MDIM];
__device__ __align__(256) __nv_bfloat16 g_q1[(size_t)BQ * MDIM];
__device__ __align__(256) __nv_bfloat16 g_q2[(size_t)BQ * MDIM];
__device__ __align__(256) __nv_bfloat16 g_k1[(size_t)NCTX * MDIM];
__device__ __align__(256) __nv_bfloat16 g_k2[(size_t)NCTX * MDIM];
__device__ __align__(256) __nv_bfloat16 g_v1t[(size_t)MDIM * NCTX];
__device__ __align__(256) __nv_bfloat16 g_v2t[(size_t)MDIM * NCTX];
__device__ __align__(256) float         g_S [(size_t)BQ * NCTX];
__device__ __align__(256) __nv_bfloat16 g_P1[(size_t)BQ * NCTX];
__device__ __align__(256) __nv_bfloat16 g_P2[(size_t)BQ * NCTX];
__device__ __align__(256) float         g_O [(size_t)BQ * MDIM];

// ===========================================================================
// Shared HMMA 128x256 mainloop body (2-split, 3 products), used by the kv
// kernel (grid.z selects B/output) and the generic S/O kernel.
// smem/stage 48KB: A1@0 A2@8K B1@16K B2@32K.
// ===========================================================================
#define STG 3
#define L2_STAGE 49152

struct L2Out {
    float acc[4][8][4];
};

__device__ __forceinline__ void l2_mainloop(
    char* smem, const __nv_bfloat16* A1, const __nv_bfloat16* A2,
    const __nv_bfloat16* B1, const __nv_bfloat16* B2,
    int bx, int by, int Kd, L2Out& o)
{
    const int tid  = threadIdx.x;
    const int lane = tid & 31;
    const int wid  = tid >> 5;
    const int wm   = wid & 1;
    const int wn   = wid >> 1;

    const uint32_t sbase = smem_u32(smem);
    const int nstages = Kd >> 5;

    const int lr = tid >> 2, lc = tid & 3;
    const uint32_t aso0 = SW((uint32_t)(lr * 64 + lc * 16));
    const uint32_t aso1 = SW((uint32_t)((lr + 64) * 64 + lc * 16));
    uint32_t bso[4];
    #pragma unroll
    for (int h = 0; h < 4; h++) bso[h] = SW((uint32_t)((lr + h * 64) * 64 + lc * 16));
    const size_t ag0 = ((size_t)by * 128 + lr) * Kd + lc * 8;
    const size_t bg0 = ((size_t)bx * 256 + lr) * Kd + lc * 8;
    const size_t rstep = (size_t)64 * Kd;

    const int a_r = lane & 15;
    const int a_h = (lane >> 4) * 16;
    const int b_r = (lane & 7) | ((lane >> 1) & 8);
    const int b_h = ((lane >> 3) & 1) * 16;

    #pragma unroll
    for (int i = 0; i < 4; i++)
        #pragma unroll
        for (int j = 0; j < 8; j++)
            #pragma unroll
            for (int q = 0; q < 4; q++) o.acc[i][j][q] = 0.0f;

    auto issue = [&](int s) {
        const uint32_t sb = sbase + (uint32_t)((s % STG) * L2_STAGE);
        const size_t kb = (size_t)s * 32;
        cp_async16(sb + aso0,        A1 + ag0 + kb);
        cp_async16(sb + aso1,        A1 + ag0 + rstep + kb);
        cp_async16(sb + 8192 + aso0, A2 + ag0 + kb);
        cp_async16(sb + 8192 + aso1, A2 + ag0 + rstep + kb);
        #pragma unroll
        for (int h = 0; h < 4; h++) {
            cp_async16(sb + 16384 + bso[h], B1 + bg0 + h * rstep + kb);
            cp_async16(sb + 32768 + bso[h], B2 + bg0 + h * rstep + kb);
        }
        cp_commit();
    };

    issue(0);
    if (nstages > 1) issue(1);

    for (int s = 0; s < nstages; s++) {
        if (s + 2 < nstages) issue(s + 2);
        const int after = nstages - 1 - s;
        if (after >= 2)      asm volatile("cp.async.wait_group 2;" ::: "memory");
        else if (after == 1) asm volatile("cp.async.wait_group 1;" ::: "memory");
        else                 asm volatile("cp.async.wait_group 0;" ::: "memory");
        __syncthreads();

        const uint32_t sb = sbase + (uint32_t)((s % STG) * L2_STAGE);
        #pragma unroll
        for (int kk = 0; kk < 2; kk++) {
            uint32_t a1f[4][4], a2f[4][4], bf[4][4];
            #pragma unroll
            for (int tm = 0; tm < 4; tm++) {
                const uint32_t off = SW((uint32_t)((wm * 64 + tm * 16 + a_r) * 64 + kk * 32 + a_h));
                ldmx4(a1f[tm], sb + off);
                ldmx4(a2f[tm], sb + 8192 + off);
            }
            #pragma unroll
            for (int tn = 0; tn < 4; tn++) {
                const uint32_t off = SW((uint32_t)((wn * 64 + tn * 16 + b_r) * 64 + kk * 32 + b_h));
                ldmx4(bf[tn], sb + 16384 + off);
            }
            #pragma unroll
            for (int tm = 0; tm < 4; tm++)
                #pragma unroll
                for (int n8 = 0; n8 < 8; n8++)
                    mma16816(o.acc[tm][n8], a1f[tm], bf[n8 >> 1][(n8 & 1) * 2], bf[n8 >> 1][(n8 & 1) * 2 + 1]);
            #pragma unroll
            for (int tm = 0; tm < 4; tm++)
                #pragma unroll
                for (int n8 = 0; n8 < 8; n8++)
                    mma16816(o.acc[tm][n8], a2f[tm], bf[n8 >> 1][(n8 & 1) * 2], bf[n8 >> 1][(n8 & 1) * 2 + 1]);
            #pragma unroll
            for (int tn = 0; tn < 4; tn++) {
                const uint32_t off = SW((uint32_t)((wn * 64 + tn * 16 + b_r) * 64 + kk * 32 + b_h));
                ldmx4(bf[tn], sb + 32768 + off);
            }
            #pragma unroll
            for (int tm = 0; tm < 4; tm++)
                #pragma unroll
                for (int n8 = 0; n8 < 8; n8++)
                    mma16816(o.acc[tm][n8], a1f[tm], bf[n8 >> 1][(n8 & 1) * 2], bf[n8 >> 1][(n8 & 1) * 2 + 1]);
        }
        __syncthreads();
    }
}

// Generic fp32-output variant (S, O GEMMs)
__global__ __launch_bounds__(256, 1)
void hmma2_kernel(const __nv_bfloat16* __restrict__ A1, const __nv_bfloat16* __restrict__ A2,
                  const __nv_bfloat16* __restrict__ B1, const __nv_bfloat16* __restrict__ B2,
                  float* __restrict__ C, int N, int Kd, float alpha)
{
    extern __shared__ char smem[];
    const int lane = threadIdx.x & 31;
    const int wid  = threadIdx.x >> 5;
    L2Out o;
    l2_mainloop(smem, A1, A2, B1, B2, blockIdx.x, blockIdx.y, Kd, o);

    const int crow0 = blockIdx.y * 128 + (wid & 1) * 64 + (lane >> 2);
    const int ccol0 = blockIdx.x * 256 + (wid >> 1) * 64 + (lane & 3) * 2;
    #pragma unroll
    for (int tm = 0; tm < 4; tm++)
        #pragma unroll
        for (int n8 = 0; n8 < 8; n8++) {
            const int cc = ccol0 + n8 * 8;
            #pragma unroll
            for (int half = 0; half < 2; half++) {
                const size_t off = (size_t)(crow0 + tm * 16 + half * 8) * N + cc;
                *(float2*)(C + off) = make_float2(alpha * o.acc[tm][n8][half * 2],
                                                  alpha * o.acc[tm][n8][half * 2 + 1]);
            }
        }
}

// Fused k/v kernel: blockIdx.z = 0 -> k (bf16 split out), 1 -> v (fp32 out)
__global__ __launch_bounds__(256, 1)
void hmma2_kv_kernel(const __nv_bfloat16* __restrict__ A1, const __nv_bfloat16* __restrict__ A2,
                     const __nv_bfloat16* Bk1, const __nv_bfloat16* Bk2,
                     const __nv_bfloat16* Bv1, const __nv_bfloat16* Bv2,
                     __nv_bfloat16* __restrict__ Kh, __nv_bfloat16* __restrict__ Kl,
                     float* __restrict__ V, int N, int Kd)
{
    extern __shared__ char smem[];
    const int lane = threadIdx.x & 31;
    const int wid  = threadIdx.x >> 5;
    const bool isv = (blockIdx.z != 0);
    L2Out o;
    l2_mainloop(smem, A1, A2, isv ? Bv1 : Bk1, isv ? Bv2 : Bk2,
                blockIdx.x, blockIdx.y, Kd, o);

    const int crow0 = blockIdx.y * 128 + (wid & 1) * 64 + (lane >> 2);
    const int ccol0 = blockIdx.x * 256 + (wid >> 1) * 64 + (lane & 3) * 2;
    #pragma unroll
    for (int tm = 0; tm < 4; tm++)
        #pragma unroll
        for (int n8 = 0; n8 < 8; n8++) {
            const int cc = ccol0 + n8 * 8;
            #pragma unroll
            for (int half = 0; half < 2; half++) {
                const size_t off = (size_t)(crow0 + tm * 16 + half * 8) * N + cc;
                const float v0 = o.acc[tm][n8][half * 2];
                const float v1 = o.acc[tm][n8][half * 2 + 1];
                if (isv) {
                    *(float2*)(V + off) = make_float2(v0, v1);
                } else {
                    const __nv_bfloat16 h0 = __float2bfloat16(v0);
                    const __nv_bfloat16 h1 = __float2bfloat16(v1);
                    Kh[off] = h0; Kh[off + 1] = h1;
                    Kl[off]     = __float2bfloat16(v0 - __bfloat162float(h0));
                    Kl[off + 1] = __float2bfloat16(v1 - __bfloat162float(h1));
                }
            }
        }
}

// ===========================================================================
// L3 HMMA GEMM (q): C = (A1+A2+A3)@(B1+B2+B3)^T, 6 products.
// Block 128x128, 8 warps (2m x 4n), warp tile 64x32, BK=32, STG=3.
// ===========================================================================
#define L3_STAGE 49152

__global__ __launch_bounds__(256, 1)
void hmma3_kernel(const __nv_bfloat16* __restrict__ A1, const __nv_bfloat16* __restrict__ A2,
                  const __nv_bfloat16* __restrict__ A3,
                  const __nv_bfloat16* __restrict__ B1, const __nv_bfloat16* __restrict__ B2,
                  const __nv_bfloat16* __restrict__ B3,
                  float* __restrict__ C, __nv_bfloat16* __restrict__ Ch, __nv_bfloat16* __restrict__ Cl,
                  int N, int Kd)
{
    extern __shared__ char smem[];
    const int tid  = threadIdx.x;
    const int lane = tid & 31;
    const int wid  = tid >> 5;
    const int wm   = wid & 1;
    const int wn   = wid >> 1;
    const int bx = blockIdx.x, by = blockIdx.y;

    const uint32_t sbase = smem_u32(smem);
    const int nstages = Kd >> 5;

    const int lr = tid >> 2, lc = tid & 3;
    const uint32_t so0 = SW((uint32_t)(lr * 64 + lc * 16));
    const uint32_t so1 = SW((uint32_t)((lr + 64) * 64 + lc * 16));
    const size_t ag0 = ((size_t)by * 128 + lr) * Kd + lc * 8;
    const size_t bg0 = ((size_t)bx * 128 + lr) * Kd + lc * 8;
    const size_t rstep = (size_t)64 * Kd;

    const int a_r = lane & 15;
    const int a_h = (lane >> 4) * 16;
    const int b_r = (lane & 7) | ((lane >> 1) & 8);
    const int b_h = ((lane >> 3) & 1) * 16;

    float acc[4][4][4];
    #pragma unroll
    for (int i = 0; i < 4; i++)
        #pragma unroll
        for (int j = 0; j < 4; j++)
            #pragma unroll
            for (int q = 0; q < 4; q++) acc[i][j][q] = 0.0f;

    auto issue = [&](int s) {
        const uint32_t sb = sbase + (uint32_t)((s % STG) * L3_STAGE);
        const size_t kb = (size_t)s * 32;
        cp_async16(sb + so0,         A1 + ag0 + kb);
        cp_async16(sb + so1,         A1 + ag0 + rstep + kb);
        cp_async16(sb + 8192 + so0,  A2 + ag0 + kb);
        cp_async16(sb + 8192 + so1,  A2 + ag0 + rstep + kb);
        cp_async16(sb + 16384 + so0, A3 + ag0 + kb);
        cp_async16(sb + 16384 + so1, A3 + ag0 + rstep + kb);
        cp_async16(sb + 24576 + so0, B1 + bg0 + kb);
        cp_async16(sb + 24576 + so1, B1 + bg0 + rstep + kb);
        cp_async16(sb + 32768 + so0, B2 + bg0 + kb);
        cp_async16(sb + 32768 + so1, B2 + bg0 + rstep + kb);
        cp_async16(sb + 40960 + so0, B3 + bg0 + kb);
        cp_async16(sb + 40960 + so1, B3 + bg0 + rstep + kb);
        cp_commit();
    };

    issue(0);
    if (nstages > 1) issue(1);

    for (int s = 0; s < nstages; s++) {
        if (s + 2 < nstages) issue(s + 2);
        const int after = nstages - 1 - s;
        if (after >= 2)      asm volatile("cp.async.wait_group 2;" ::: "memory");
        else if (after == 1) asm volatile("cp.async.wait_group 1;" ::: "memory");
        else                 asm volatile("cp.async.wait_group 0;" ::: "memory");
        __syncthreads();

        const uint32_t sb = sbase + (uint32_t)((s % STG) * L3_STAGE);
        #pragma unroll
        for (int kk = 0; kk < 2; kk++) {
            uint32_t a1f[4][4], a2f[4][4], a3f[4][4], bf[2][4];
            #pragma unroll
            for (int tm = 0; tm < 4; tm++) {
                const uint32_t off = SW((uint32_t)((wm * 64 + tm * 16 + a_r) * 64 + kk * 32 + a_h));
                ldmx4(a1f[tm], sb + off);
                ldmx4(a2f[tm], sb + 8192 + off);
                ldmx4(a3f[tm], sb + 16384 + off);
            }
            uint32_t boff[2];
            #pragma unroll
            for (int tn = 0; tn < 2; tn++)
                boff[tn] = SW((uint32_t)((wn * 32 + tn * 16 + b_r) * 64 + kk * 32 + b_h));
            #pragma unroll
            for (int tn = 0; tn < 2; tn++) ldmx4(bf[tn], sb + 24576 + boff[tn]);
            #pragma unroll
            for (int tm = 0; tm < 4; tm++)
                #pragma unroll
                for (int n8 = 0; n8 < 4; n8++) {
                    mma16816(acc[tm][n8], a1f[tm], bf[n8 >> 1][(n8 & 1) * 2], bf[n8 >> 1][(n8 & 1) * 2 + 1]);
                    mma16816(acc[tm][n8], a2f[tm], bf[n8 >> 1][(n8 & 1) * 2], bf[n8 >> 1][(n8 & 1) * 2 + 1]);
                    mma16816(acc[tm][n8], a3f[tm], bf[n8 >> 1][(n8 & 1) * 2], bf[n8 >> 1][(n8 & 1) * 2 + 1]);
                }
            #pragma unroll
            for (int tn = 0; tn < 2; tn++) ldmx4(bf[tn], sb + 32768 + boff[tn]);
            #pragma unroll
            for (int tm = 0; tm < 4; tm++)
                #pragma unroll
                for (int n8 = 0; n8 < 4; n8++) {
                    mma16816(acc[tm][n8], a1f[tm], bf[n8 >> 1][(n8 & 1) * 2], bf[n8 >> 1][(n8 & 1) * 2 + 1]);
                    mma16816(acc[tm][n8], a2f[tm], bf[n8 >> 1][(n8 & 1) * 2], bf[n8 >> 1][(n8 & 1) * 2 + 1]);
                }
            #pragma unroll
            for (int tn = 0; tn < 2; tn++) ldmx4(bf[tn], sb + 40960 + boff[tn]);
            #pragma unroll
            for (int tm = 0; tm < 4; tm++)
                #pragma unroll
                for (int n8 = 0; n8 < 4; n8++)
                    mma16816(acc[tm][n8], a1f[tm], bf[n8 >> 1][(n8 & 1) * 2], bf[n8 >> 1][(n8 & 1) * 2 + 1]);
        }
        __syncthreads();
    }

    const int crow0 = by * 128 + wm * 64 + (lane >> 2);
    const int ccol0 = bx * 128 + wn * 32 + (lane & 3) * 2;
    #pragma unroll
    for (int tm = 0; tm < 4; tm++)
        #pragma unroll
        for (int n8 = 0; n8 < 4; n8++) {
            const int cc = ccol0 + n8 * 8;
            #pragma unroll
            for (int half = 0; half < 2; half++) {
                const size_t o = (size_t)(crow0 + tm * 16 + half * 8) * N + cc;
                const float v0 = acc[tm][n8][half * 2];
                const float v1 = acc[tm][n8][half * 2 + 1];
                *(float2*)(C + o) = make_float2(v0, v1);
                const __nv_bfloat16 h0 = __float2bfloat16(v0);
                const __nv_bfloat16 h1 = __float2bfloat16(v1);
                Ch[o] = h0; Ch[o + 1] = h1;
                Cl[o]     = __float2bfloat16(v0 - __bfloat162float(h0));
                Cl[o + 1] = __float2bfloat16(v1 - __bfloat162float(h1));
            }
        }
}

// ===========================================================================
// Vectorized split helpers (float4 in, packed bf16x2 out)
// ===========================================================================
__global__ void split_kernel(const float4* __restrict__ x,
                             uint2* __restrict__ hi, uint2* __restrict__ lo, int n4)
{
    const int i = blockIdx.x * blockDim.x + threadIdx.x;
    if (i < n4) {
        const float4 v = x[i];
        const __nv_bfloat16 h0 = __float2bfloat16(v.x), h1 = __float2bfloat16(v.y);
        const __nv_bfloat16 h2 = __float2bfloat16(v.z), h3 = __float2bfloat16(v.w);
        hi[i] = make_uint2(pack_bf2(h0, h1), pack_bf2(h2, h3));
        lo[i] = make_uint2(
            pack_bf2(__float2bfloat16(v.x - __bfloat162float(h0)),
                     __float2bfloat16(v.y - __bfloat162float(h1))),
            pack_bf2(__float2bfloat16(v.z - __bfloat162float(h2)),
                     __float2bfloat16(v.w - __bfloat162float(h3))));
    }
}

__global__ void split3_kernel(const float4* __restrict__ x,
                              uint2* __restrict__ o1, uint2* __restrict__ o2,
                              uint2* __restrict__ o3, int n4)
{
    const int i = blockIdx.x * blockDim.x + threadIdx.x;
    if (i < n4) {
        const float4 v = x[i];
        float f[4] = {v.x, v.y, v.z, v.w};
        __nv_bfloat16 a[4], b[4], c[4];
        #pragma unroll
        for (int j = 0; j < 4; j++) {
            a[j] = __float2bfloat16(f[j]);
            const float r1 = f[j] - __bfloat162float(a[j]);
            b[j] = __float2bfloat16(r1);
            c[j] = __float2bfloat16(r1 - __bfloat162float(b[j]));
        }
        o1[i] = make_uint2(pack_bf2(a[0], a[1]), pack_bf2(a[2], a[3]));
        o2[i] = make_uint2(pack_bf2(b[0], b[1]), pack_bf2(b[2], b[3]));
        o3[i] = make_uint2(pack_bf2(c[0], c[1]), pack_bf2(c[2], c[3]));
    }
}

__global__ void split_transpose_kernel(const float* __restrict__ in,
                                       __nv_bfloat16* __restrict__ hi, __nv_bfloat16* __restrict__ lo,
                                       int rows, int cols)
{
    __shared__ float tile[32][33];
    const int c0 = blockIdx.x * 32, r0 = blockIdx.y * 32;
    const int tx = threadIdx.x, ty = threadIdx.y;
    #pragma unroll
    for (int j = ty; j < 32; j += 8)
        tile[j][tx] = in[(size_t)(r0 + j) * cols + c0 + tx];
    __syncthreads();
    #pragma unroll
    for (int j = ty; j < 32; j += 8) {
        const float v = tile[tx][j];
        const __nv_bfloat16 h = __float2bfloat16(v);
        const size_t o = (size_t)(c0 + j) * rows + r0 + tx;
        hi[o] = h;
        lo[o] = __float2bfloat16(v - __bfloat162float(h));
    }
}

__global__ void split3_transpose_kernel(const float* __restrict__ in,
                                        __nv_bfloat16* __restrict__ h1, __nv_bfloat16* __restrict__ h2,
                                        __nv_bfloat16* __restrict__ h3, int rows, int cols)
{
    __shared__ float tile[32][33];
    const int c0 = blockIdx.x * 32, r0 = blockIdx.y * 32;
    const int tx = threadIdx.x, ty = threadIdx.y;
    #pragma unroll
    for (int j = ty; j < 32; j += 8)
        tile[j][tx] = in[(size_t)(r0 + j) * cols + c0 + tx];
    __syncthreads();
    #pragma unroll
    for (int j = ty; j < 32; j += 8) {
        const float v = tile[tx][j];
        const __nv_bfloat16 a = __float2bfloat16(v);
        const float r1 = v - __bfloat162float(a);
        const __nv_bfloat16 b = __float2bfloat16(r1);
        const size_t o = (size_t)(c0 + j) * rows + r0 + tx;
        h1[o] = a; h2[o] = b;
        h3[o] = __float2bfloat16(r1 - __bfloat162float(b));
    }
}

// ===========================================================================
// Row softmax -> bf16 hi/lo split
// ===========================================================================
__global__ __launch_bounds__(256)
void softmax_split_kernel(const float* __restrict__ S,
                          __nv_bfloat16* __restrict__ P1, __nv_bfloat16* __restrict__ P2)
{
    const int row = blockIdx.x;
    const int t = threadIdx.x;
    const float* Sr = S + (size_t)row * NCTX;
    __shared__ float red[256];

    float vals[NCTX / 256];
    float m = -INFINITY;
    #pragma unroll
    for (int i = 0; i < NCTX / 256; i++) {
        vals[i] = Sr[t + i * 256];
        m = fmaxf(m, vals[i]);
    }
    red[t] = m; __syncthreads();
    #pragma unroll
    for (int s = 128; s > 0; s >>= 1) {
        if (t < s) red[t] = fmaxf(red[t], red[t + s]);
        __syncthreads();
    }
    m = red[0]; __syncthreads();

    float sum = 0.0f;
    #pragma unroll
    for (int i = 0; i < NCTX / 256; i++) {
        vals[i] = __expf(vals[i] - m);
        sum += vals[i];
    }
    red[t] = sum; __syncthreads();
    #pragma unroll
    for (int s = 128; s > 0; s >>= 1) {
        if (t < s) red[t] += red[t + s];
        __syncthreads();
    }
    const float inv = 1.0f / red[0];

    #pragma unroll
    for (int i = 0; i < NCTX / 256; i++) {
        const float p = vals[i] * inv;
        const __nv_bfloat16 h = __float2bfloat16(p);
        const size_t o = (size_t)row * NCTX + t + i * 256;
        P1[o] = h;
        P2[o] = __float2bfloat16(p - __bfloat162float(h));
    }
}

// ===========================================================================
// Fused epilogue
// ===========================================================================
#define EROWS 4
__global__ __launch_bounds__(256)
void epilogue_kernel(const float* __restrict__ O, const float* __restrict__ Q,
                     const float* __restrict__ Whash, const float* __restrict__ bhash,
                     const float* __restrict__ gamma, const float* __restrict__ beta,
                     const float* __restrict__ Wcls, const float* __restrict__ bcls,
                     float* __restrict__ out)
{
    const int b0 = blockIdx.x * EROWS;
    const int t = threadIdx.x;
    __shared__ float att[EROWS][MDIM];
    __shared__ float red[256];
    __shared__ float part[4][EROWS][CDIM];
    __shared__ float code_s[EROWS][CDIM];

    for (int r = 0; r < EROWS; r++) {
        const int b = b0 + r;
        float loc[MDIM / 256];
        float s = 0.0f;
        #pragma unroll
        for (int i = 0; i < MDIM / 256; i++) {
            const int m = t + i * 256;
            loc[i] = __fadd_rn(__fmul_rn(0.1f, O[(size_t)b * MDIM + m]),
                               Q[(size_t)b * MDIM + m]);
            s += loc[i];
        }
        red[t] = s; __syncthreads();
        #pragma unroll
        for (int st = 128; st > 0; st >>= 1) {
            if (t < st) red[t] += red[t + st];
            __syncthreads();
        }
        const float mu = red[0] * (1.0f / MDIM);
        __syncthreads();

        float vs = 0.0f;
        #pragma unroll
        for (int i = 0; i < MDIM / 256; i++) {
            const float d = loc[i] - mu;
            vs += d * d;
        }
        red[t] = vs; __syncthreads();
        #pragma unroll
        for (int st = 128; st > 0; st >>= 1) {
            if (t < st) red[t] += red[t + st];
            __syncthreads();
        }
        const float var = red[0] * (1.0f / MDIM);
        const float rs = 1.0f / sqrtf(var + 1e-6f);
        __syncthreads();

        #pragma unroll
        for (int i = 0; i < MDIM / 256; i++) {
            const int m = t + i * 256;
            att[r][m] = (loc[i] - mu) * rs * gamma[m] + beta[m];
        }
    }
    __syncthreads();

    {
        const int c = t & 63, seg = t >> 6;
        float acc[EROWS] = {0.f, 0.f, 0.f, 0.f};
        const int m0 = seg * (MDIM / 4);
        for (int m = m0; m < m0 + MDIM / 4; m++) {
            const float w = Whash[m * CDIM + c];
            #pragma unroll
            for (int r = 0; r < EROWS; r++) acc[r] += att[r][m] * w;
        }
        #pragma unroll
        for (int r = 0; r < EROWS; r++) part[seg][r][c] = acc[r];
    }
    __syncthreads();

    {
        const int c = t & 63, r = t >> 6;
        const float fh = bhash[c] + part[0][r][c] + part[1][r][c]
                                  + part[2][r][c] + part[3][r][c];
        const float prob = 1.0f / (1.0f + expf(-fh));
        const float hard = (prob > 0.5f) ? 1.0f : 0.0f;
        code_s[r][c] = hard;
        const int b = b0 + r;
        out[(size_t)b * CDIM + c] = hard;
        out[(size_t)BQ * CDIM + (size_t)b * CDIM + c] = prob;
    }
    __syncthreads();

    for (int idx = t; idx < EROWS * KCLS; idx += 256) {
        const int r = idx / KCLS, kk = idx % KCLS;
        float acc = bcls[kk];
        #pragma unroll
        for (int c = 0; c < CDIM; c++)
            acc += code_s[r][c] * Wcls[c * KCLS + kk];
        out[(size_t)BQ * CDIM * 2 + (size_t)(b0 + r) * KCLS + kk] = acc;
    }
}

// ===========================================================================
extern "C" void kernel_launch(void* const* d_in, const int* in_sizes, int n_in,
                              void* d_out, int out_size)
{
    const float* feat   = (const float*)d_in[0];
    const float* emb    = (const float*)d_in[1];
    const float* W_k    = (const float*)d_in[2];
    const float* W_v    = (const float*)d_in[3];
    const float* W_q    = (const float*)d_in[4];
    const float* W_hash = (const float*)d_in[5];
    const float* b_hash = (const float*)d_in[6];
    const float* ln_g   = (const float*)d_in[7];
    const float* ln_b   = (const float*)d_in[8];
    const float* W_cls  = (const float*)d_in[9];
    const float* b_cls  = (const float*)d_in[10];
    float* out = (float*)d_out;

    cudaFuncSetAttribute(hmma2_kernel,    cudaFuncAttributeMaxDynamicSharedMemorySize, STG * L2_STAGE);
    cudaFuncSetAttribute(hmma2_kv_kernel, cudaFuncAttributeMaxDynamicSharedMemorySize, STG * L2_STAGE);
    cudaFuncSetAttribute(hmma3_kernel,    cudaFuncAttributeMaxDynamicSharedMemorySize, STG * L3_STAGE);

    __nv_bfloat16 *pe1, *pe2, *pwk1, *pwk2, *pwv1, *pwv2;
    __nv_bfloat16 *pf1, *pf2, *pf3, *pwq1, *pwq2, *pwq3;
    __nv_bfloat16 *pq1, *pq2, *pk1, *pk2, *pv1, *pv2, *pP1, *pP2;
    float *pv, *pq, *pS, *pO;
    cudaGetSymbolAddress((void**)&pe1, g_emb1);  cudaGetSymbolAddress((void**)&pe2, g_emb2);
    cudaGetSymbolAddress((void**)&pwk1, g_wk1t); cudaGetSymbolAddress((void**)&pwk2, g_wk2t);
    cudaGetSymbolAddress((void**)&pwv1, g_wv1t); cudaGetSymbolAddress((void**)&pwv2, g_wv2t);
    cudaGetSymbolAddress((void**)&pf1, g_f1);    cudaGetSymbolAddress((void**)&pf2, g_f2);
    cudaGetSymbolAddress((void**)&pf3, g_f3);
    cudaGetSymbolAddress((void**)&pwq1, g_wq1t); cudaGetSymbolAddress((void**)&pwq2, g_wq2t);
    cudaGetSymbolAddress((void**)&pwq3, g_wq3t);
    cudaGetSymbolAddress((void**)&pq1, g_q1);    cudaGetSymbolAddress((void**)&pq2, g_q2);
    cudaGetSymbolAddress((void**)&pk1, g_k1);    cudaGetSymbolAddress((void**)&pk2, g_k2);
    cudaGetSymbolAddress((void**)&pv1, g_v1t);   cudaGetSymbolAddress((void**)&pv2, g_v2t);
    cudaGetSymbolAddress((void**)&pP1, g_P1);    cudaGetSymbolAddress((void**)&pP2, g_P2);
    cudaGetSymbolAddress((void**)&pv, g_v);      cudaGetSymbolAddress((void**)&pq, g_q);
    cudaGetSymbolAddress((void**)&pS, g_S);      cudaGetSymbolAddress((void**)&pO, g_O);

    const size_t smem2 = STG * L2_STAGE;
    const size_t smem3 = STG * L3_STAGE;

    // input splits (vectorized)
    split_kernel<<<(NCTX * DDIM / 4) / 256, 256>>>(
        (const float4*)emb, (uint2*)pe1, (uint2*)pe2, NCTX * DDIM / 4);
    split_transpose_kernel<<<dim3(MDIM / 32, DDIM / 32), dim3(32, 8)>>>(W_k, pwk1, pwk2, DDIM, MDIM);
    split_transpose_kernel<<<dim3(MDIM / 32, DDIM / 32), dim3(32, 8)>>>(W_v, pwv1, pwv2, DDIM, MDIM);
    split3_kernel<<<(BQ * DDIM / 4) / 256, 256>>>(
        (const float4*)feat, (uint2*)pf1, (uint2*)pf2, (uint2*)pf3, BQ * DDIM / 4);
    split3_transpose_kernel<<<dim3(MDIM / 32, DDIM / 32), dim3(32, 8)>>>(W_q, pwq1, pwq2, pwq3, DDIM, MDIM);

    // k (split out) + v (fp32 out) fused into one launch (grid.z)
    hmma2_kv_kernel<<<dim3(MDIM / 256, NCTX / 128, 2), 256, smem2>>>(
        pe1, pe2, pwk1, pwk2, pwv1, pwv2, pk1, pk2, pv, MDIM, DDIM);

    // q = feat @ W_q (triple split, 6 products) -> fp32 + hi/lo split
    hmma3_kernel<<<dim3(MDIM / 128, BQ / 128), 256, smem3>>>(
        pf1, pf2, pf3, pwq1, pwq2, pwq3, pq, pq1, pq2, MDIM, DDIM);

    split_transpose_kernel<<<dim3(MDIM / 32, NCTX / 32), dim3(32, 8)>>>(pv, pv1, pv2, NCTX, MDIM);

    // S = q @ k^T / 32
    hmma2_kernel<<<dim3(NCTX / 256, BQ / 128), 256, smem2>>>(
        pq1, pq2, pk1, pk2, pS, NCTX, MDIM, 0.03125f);

    softmax_split_kernel<<<BQ, 256>>>(pS, pP1, pP2);

    // O = P @ v
    hmma2_kernel<<<dim3(MDIM / 256, BQ / 128), 256, smem2>>>(
        pP1, pP2, pv1, pv2, pO, MDIM, NCTX, 1.0f);

    epilogue_kernel<<<BQ / EROWS, 256>>>(pO, pq, W_hash, b_hash, ln_g, ln_b, W_cls, b_cls, out);
}